// round 7
// baseline (speedup 1.0000x reference)
#include <cuda_runtime.h>
#include <cuda_bf16.h>
#include <cstdint>
#include <cstddef>

// ============================================================================
// DecagonModel — R7 (R6 resubmit; even-round container flake, content-neutral)
// bf16-split mma.sync GEMMs, 2 CTA/SM; COO SpMM via red.global.add.v4.f32.
// ============================================================================

#define KN0 30000
#define KN1 6000
#define KF  1024
#define KH  512
#define LDO 1536

__device__ float g_tmp[KN0 * KH];
__device__ float g_e00[KN0 * KH];
__device__ float g_e01[KN1 * KH];
__device__ float g_e20[KN0 * KH];
__device__ float g_e21[KN1 * KH];

__device__ __nv_bfloat16 g_f0h[KN0 * KF], g_f0l[KN0 * KF];
__device__ __nv_bfloat16 g_f1h[KN1 * KF], g_f1l[KN1 * KF];
__device__ __nv_bfloat16 g_e00h[KN0 * KH], g_e00l[KN0 * KH];
__device__ __nv_bfloat16 g_e01h[KN1 * KH], g_e01l[KN1 * KH];
__device__ __nv_bfloat16 g_e20h[KN0 * KH], g_e20l[KN0 * KH];
__device__ __nv_bfloat16 g_e21h[KN1 * KH], g_e21l[KN1 * KH];

#define WT_TOTAL (5 * KH * KF + 10 * KH * KH)
__device__ __nv_bfloat16 g_wth[WT_TOTAL], g_wtl[WT_TOTAL];

// ---------------- helpers ---------------------------------------------------
__device__ __forceinline__ uint32_t smem_u32(const void* p) {
    uint32_t a;
    asm("{ .reg .u64 t; cvta.to.shared.u64 t, %1; cvt.u32.u64 %0, t; }"
        : "=r"(a) : "l"(p));
    return a;
}
__device__ __forceinline__ void cpa16(uint32_t dst, const void* src, bool v) {
    asm volatile("cp.async.cg.shared.global [%0], [%1], 16, %2;"
                 :: "r"(dst), "l"(src), "r"(v ? 16 : 0) : "memory");
}
__device__ __forceinline__ void ldsm4(uint32_t& r0, uint32_t& r1, uint32_t& r2,
                                      uint32_t& r3, uint32_t addr) {
    asm volatile("ldmatrix.sync.aligned.m8n8.x4.shared.b16 {%0,%1,%2,%3}, [%4];"
                 : "=r"(r0), "=r"(r1), "=r"(r2), "=r"(r3) : "r"(addr));
}
__device__ __forceinline__ void mma16816(float& c0, float& c1, float& c2, float& c3,
                                         uint32_t a0, uint32_t a1, uint32_t a2, uint32_t a3,
                                         uint32_t b0, uint32_t b1) {
    asm volatile(
        "mma.sync.aligned.m16n8k16.row.col.f32.bf16.bf16.f32 "
        "{%0,%1,%2,%3}, {%4,%5,%6,%7}, {%8,%9}, {%0,%1,%2,%3};"
        : "+f"(c0), "+f"(c1), "+f"(c2), "+f"(c3)
        : "r"(a0), "r"(a1), "r"(a2), "r"(a3), "r"(b0), "r"(b1));
}
__device__ __forceinline__ uint32_t swz(int r, int cbyte) {
    return (uint32_t)(r * 64 + (cbyte ^ (((r >> 1) & 3) << 4)));
}

// ----------------------------------------------------------------------------
// GEMM: C[M,512] = (Ah+Al)[M,K] @ (Bh+Bl)^T, B stored [512,K] bf16 row-major.
// CTA 128x128, BK=32, 3-stage cp.async, 256 threads, warp tile 64x32.
// __launch_bounds__(256,2): 2 CTAs/SM (regs<=128, smem 2x96KB=192KB).
// ----------------------------------------------------------------------------
#define STG_BYTES 32768u          // Ah 8K | Al 8K | Bh 8K | Bl 8K
#define GEMM_SMEM (3 * STG_BYTES)

__global__ __launch_bounds__(256, 2) void gemm_mma(
    const __nv_bfloat16* __restrict__ Ah, const __nv_bfloat16* __restrict__ Al,
    const __nv_bfloat16* __restrict__ Bh, const __nv_bfloat16* __restrict__ Bl,
    float* __restrict__ C, int M, int K)
{
    extern __shared__ char dyn_smem[];
    const uint32_t sbase = smem_u32(dyn_smem);

    const int tid  = threadIdx.x;
    const int wid  = tid >> 5;
    const int lane = tid & 31;
    const int bm   = blockIdx.y * 128;
    const int bn   = blockIdx.x * 128;
    const int wm   = (wid & 1) * 64;
    const int wn   = (wid >> 1) * 32;

    const int NC = K >> 5;

    auto load_stage = [&](int c) {
        const uint32_t st = sbase + (uint32_t)(c % 3) * STG_BYTES;
        const int k0 = c << 5;
#pragma unroll
        for (int it = 0; it < 8; it++) {
            int seg  = it * 256 + tid;
            int reg  = seg >> 9;                 // 0 Ah, 1 Al, 2 Bh, 3 Bl
            int r    = (seg & 511) >> 2;
            int cs   = seg & 3;
            uint32_t dst = st + (uint32_t)reg * 8192u + swz(r, cs * 16);
            const __nv_bfloat16* src;
            bool v = true;
            if (reg < 2) {
                int gr = bm + r;
                v = gr < M; if (!v) gr = 0;
                src = (reg == 0 ? Ah : Al) + (size_t)gr * K + k0 + cs * 8;
            } else {
                src = (reg == 2 ? Bh : Bl) + (size_t)(bn + r) * K + k0 + cs * 8;
            }
            cpa16(dst, src, v);
        }
        asm volatile("cp.async.commit_group;" ::: "memory");
    };

    float acc[4][4][4];
#pragma unroll
    for (int i = 0; i < 4; i++)
#pragma unroll
        for (int j = 0; j < 4; j++)
#pragma unroll
            for (int q = 0; q < 4; q++) acc[i][j][q] = 0.f;

    load_stage(0);
    load_stage(1);

    const int mi  = lane >> 3;
    const int r8  = lane & 7;
    const int aro = (mi & 1) * 8 + r8;
    const int akb = (mi >> 1) * 16;
    const int bro = (mi & 1) * 8 + r8;
    const int bkb = (mi >> 1) * 16;

    for (int c = 0; c < NC; c++) {
        asm volatile("cp.async.wait_group 1;" ::: "memory");
        __syncthreads();   // orders: prev chunk's reads done AND this stage's data visible
        if (c + 2 < NC) load_stage(c + 2);

        const uint32_t st  = sbase + (uint32_t)(c % 3) * STG_BYTES;
        const uint32_t sAh = st, sAl = st + 8192, sBh = st + 16384, sBl = st + 24576;

#pragma unroll
        for (int s = 0; s < 2; s++) {
            const int kb = s * 32;
            uint32_t ah[4][4], al[4][4], bhf[4][2], blf[4][2];
            #pragma unroll
            for (int i = 0; i < 4; i++)
                ldsm4(ah[i][0], ah[i][1], ah[i][2], ah[i][3],
                      sAh + swz(wm + i * 16 + aro, kb + akb));
            #pragma unroll
            for (int j2 = 0; j2 < 2; j2++) {
                uint32_t r0, r1, r2, r3;
                ldsm4(r0, r1, r2, r3, sBh + swz(wn + j2 * 16 + bro, kb + bkb));
                bhf[j2 * 2][0]     = r0; bhf[j2 * 2][1]     = r2;
                bhf[j2 * 2 + 1][0] = r1; bhf[j2 * 2 + 1][1] = r3;
            }
            #pragma unroll
            for (int i = 0; i < 4; i++)
                #pragma unroll
                for (int j = 0; j < 4; j++)
                    mma16816(acc[i][j][0], acc[i][j][1], acc[i][j][2], acc[i][j][3],
                             ah[i][0], ah[i][1], ah[i][2], ah[i][3],
                             bhf[j][0], bhf[j][1]);
            #pragma unroll
            for (int j2 = 0; j2 < 2; j2++) {
                uint32_t r0, r1, r2, r3;
                ldsm4(r0, r1, r2, r3, sBl + swz(wn + j2 * 16 + bro, kb + bkb));
                blf[j2 * 2][0]     = r0; blf[j2 * 2][1]     = r2;
                blf[j2 * 2 + 1][0] = r1; blf[j2 * 2 + 1][1] = r3;
            }
            #pragma unroll
            for (int i = 0; i < 4; i++)
                #pragma unroll
                for (int j = 0; j < 4; j++)
                    mma16816(acc[i][j][0], acc[i][j][1], acc[i][j][2], acc[i][j][3],
                             ah[i][0], ah[i][1], ah[i][2], ah[i][3],
                             blf[j][0], blf[j][1]);
            #pragma unroll
            for (int i = 0; i < 4; i++)
                ldsm4(al[i][0], al[i][1], al[i][2], al[i][3],
                      sAl + swz(wm + i * 16 + aro, kb + akb));
            #pragma unroll
            for (int i = 0; i < 4; i++)
                #pragma unroll
                for (int j = 0; j < 4; j++)
                    mma16816(acc[i][j][0], acc[i][j][1], acc[i][j][2], acc[i][j][3],
                             al[i][0], al[i][1], al[i][2], al[i][3],
                             bhf[j][0], bhf[j][1]);
        }
        // no trailing __syncthreads: loop-top sync covers stage-reuse hazard
    }

    const int lm = lane >> 2, ln = (lane & 3) * 2;
#pragma unroll
    for (int i = 0; i < 4; i++) {
#pragma unroll
        for (int j = 0; j < 4; j++) {
            int m0 = bm + wm + i * 16 + lm;
            int n0 = bn + wn + j * 8 + ln;
            if (m0 < M)
                *(float2*)(C + (size_t)m0 * KH + n0) =
                    make_float2(acc[i][j][0], acc[i][j][1]);
            if (m0 + 8 < M)
                *(float2*)(C + (size_t)(m0 + 8) * KH + n0) =
                    make_float2(acc[i][j][2], acc[i][j][3]);
        }
    }
}

// ----------------------------------------------------------------------------
// SpMM (COO, warp/edge) with red.global.add.v4.f32
// ----------------------------------------------------------------------------
__global__ __launch_bounds__(256) void spmm_edges(
    const int* __restrict__ row, const int* __restrict__ col,
    const float* __restrict__ val, const float* __restrict__ x,
    float* __restrict__ out, int E, int ldo)
{
    int warp = (blockIdx.x * blockDim.x + threadIdx.x) >> 5;
    int lane = threadIdx.x & 31;
    if (warp >= E) return;
    const int   r = row[warp];
    const int   c = col[warp];
    const float v = val[warp];
    const float4* xr   = reinterpret_cast<const float4*>(x + (size_t)c * KH);
    float*        orow = out + (size_t)r * ldo;
#pragma unroll
    for (int i = 0; i < 4; i++) {
        float4 t = xr[lane + i * 32];
        float* p = orow + (size_t)(lane + i * 32) * 4;
        asm volatile("red.global.add.v4.f32 [%0], {%1, %2, %3, %4};"
                     :: "l"(p), "f"(t.x * v), "f"(t.y * v), "f"(t.z * v), "f"(t.w * v)
                     : "memory");
    }
}

// ----------------------------------------------------------------------------
// Converters / epilogues
// ----------------------------------------------------------------------------
__device__ __forceinline__ void split2(float a, float b, __nv_bfloat162& h, __nv_bfloat162& l)
{
    __nv_bfloat16 ha = __float2bfloat16(a), hb = __float2bfloat16(b);
    h = __nv_bfloat162(ha, hb);
    l = __nv_bfloat162(__float2bfloat16(a - __bfloat162float(ha)),
                       __float2bfloat16(b - __bfloat162float(hb)));
}

__global__ void split_k(const float* __restrict__ x,
                        __nv_bfloat16* __restrict__ h, __nv_bfloat16* __restrict__ l, size_t n4)
{
    size_t i = blockIdx.x * (size_t)blockDim.x + threadIdx.x;
    if (i >= n4) return;
    float4 t = reinterpret_cast<const float4*>(x)[i];
    __nv_bfloat162 h0, l0, h1, l1;
    split2(t.x, t.y, h0, l0);
    split2(t.z, t.w, h1, l1);
    reinterpret_cast<__nv_bfloat162*>(h)[i * 2]     = h0;
    reinterpret_cast<__nv_bfloat162*>(h)[i * 2 + 1] = h1;
    reinterpret_cast<__nv_bfloat162*>(l)[i * 2]     = l0;
    reinterpret_cast<__nv_bfloat162*>(l)[i * 2 + 1] = l1;
}

__global__ void wt_split(const float* __restrict__ W,
                         __nv_bfloat16* __restrict__ th, __nv_bfloat16* __restrict__ tl, int K)
{
    __shared__ float t[32][33];
    int kb = blockIdx.x * 32, nb = blockIdx.y * 32;
    int x = threadIdx.x, y = threadIdx.y;
#pragma unroll
    for (int i = 0; i < 32; i += 8)
        t[y + i][x] = W[(size_t)(kb + y + i) * KH + nb + x];
    __syncthreads();
#pragma unroll
    for (int i = 0; i < 32; i += 8) {
        int n = nb + y + i, k = kb + x;
        float v = t[x][y + i];
        __nv_bfloat16 hb = __float2bfloat16(v);
        th[(size_t)n * K + k] = hb;
        tl[(size_t)n * K + k] = __float2bfloat16(v - __bfloat162float(hb));
    }
}

__global__ void zero_kernel(float* __restrict__ p, size_t n4)
{
    size_t i = blockIdx.x * (size_t)blockDim.x + threadIdx.x;
    if (i < n4) reinterpret_cast<float4*>(p)[i] = make_float4(0.f, 0.f, 0.f, 0.f);
}

__global__ void zero_cols(float* __restrict__ out, int nrows)
{
    int idx = blockIdx.x * blockDim.x + threadIdx.x;
    if (idx >= nrows * 128) return;
    int r = idx >> 7, c = idx & 127;
    reinterpret_cast<float4*>(out + (size_t)r * LDO + 1024)[c] =
        make_float4(0.f, 0.f, 0.f, 0.f);
}

__global__ void relu_dual_split(float* __restrict__ e, float* __restrict__ outbase,
                                __nv_bfloat16* __restrict__ eh, __nv_bfloat16* __restrict__ el,
                                int n)
{
    int idx = blockIdx.x * blockDim.x + threadIdx.x;
    if (idx >= n * 128) return;
    float4 t = reinterpret_cast<float4*>(e)[idx];
    t.x = fmaxf(t.x, 0.f); t.y = fmaxf(t.y, 0.f);
    t.z = fmaxf(t.z, 0.f); t.w = fmaxf(t.w, 0.f);
    reinterpret_cast<float4*>(e)[idx] = t;
    int r = idx >> 7, c = idx & 127;
    float4* o = reinterpret_cast<float4*>(outbase + (size_t)r * LDO);
    o[c]       = t;
    o[c + 128] = t;
    __nv_bfloat162 h0, l0, h1, l1;
    split2(t.x, t.y, h0, l0);
    split2(t.z, t.w, h1, l1);
    reinterpret_cast<__nv_bfloat162*>(eh)[idx * 2]     = h0;
    reinterpret_cast<__nv_bfloat162*>(eh)[idx * 2 + 1] = h1;
    reinterpret_cast<__nv_bfloat162*>(el)[idx * 2]     = l0;
    reinterpret_cast<__nv_bfloat162*>(el)[idx * 2 + 1] = l1;
}

__global__ void relu_split(float* __restrict__ e,
                           __nv_bfloat16* __restrict__ eh, __nv_bfloat16* __restrict__ el,
                           size_t n4)
{
    size_t i = blockIdx.x * (size_t)blockDim.x + threadIdx.x;
    if (i >= n4) return;
    float4 t = reinterpret_cast<float4*>(e)[i];
    t.x = fmaxf(t.x, 0.f); t.y = fmaxf(t.y, 0.f);
    t.z = fmaxf(t.z, 0.f); t.w = fmaxf(t.w, 0.f);
    reinterpret_cast<float4*>(e)[i] = t;
    __nv_bfloat162 h0, l0, h1, l1;
    split2(t.x, t.y, h0, l0);
    split2(t.z, t.w, h1, l1);
    reinterpret_cast<__nv_bfloat162*>(eh)[i * 2]     = h0;
    reinterpret_cast<__nv_bfloat162*>(eh)[i * 2 + 1] = h1;
    reinterpret_cast<__nv_bfloat162*>(el)[i * 2]     = l0;
    reinterpret_cast<__nv_bfloat162*>(el)[i * 2 + 1] = l1;
}

// ----------------------------------------------------------------------------
// Host orchestration
// ----------------------------------------------------------------------------
static size_t wt_off(int l, int r)
{
    if (l == 0) return (size_t)r * KH * KF;
    return (size_t)5 * KH * KF + (size_t)((l - 1) * 5 + r) * KH * KH;
}

extern "C" void kernel_launch(void* const* d_in, const int* in_sizes, int n_in,
                              void* d_out, int out_size)
{
    const float* feat0 = (const float*)d_in[0];
    const float* feat1 = (const float*)d_in[1];

    const int*   a_row[5]; const int* a_col[5]; const float* a_val[5]; int Ecnt[5];
    for (int i = 0; i < 5; i++) {
        a_row[i] = (const int*)d_in[2 + 3 * i];
        a_col[i] = (const int*)d_in[3 + 3 * i];
        a_val[i] = (const float*)d_in[4 + 3 * i];
        Ecnt[i]  = in_sizes[2 + 3 * i];
    }
    const float* W[3][5];
    for (int r = 0; r < 5; r++)
        for (int l = 0; l < 3; l++)
            W[l][r] = (const float*)d_in[17 + 3 * r + l];

    float *tmp, *e00, *e01, *e20, *e21;
    __nv_bfloat16 *f0h, *f0l, *f1h, *f1l;
    __nv_bfloat16 *e00h, *e00l, *e01h, *e01l, *e20h, *e20l, *e21h, *e21l;
    __nv_bfloat16 *wth, *wtl;
    {
        void* p;
        cudaGetSymbolAddress(&p, g_tmp);  tmp  = (float*)p;
        cudaGetSymbolAddress(&p, g_e00);  e00  = (float*)p;
        cudaGetSymbolAddress(&p, g_e01);  e01  = (float*)p;
        cudaGetSymbolAddress(&p, g_e20);  e20  = (float*)p;
        cudaGetSymbolAddress(&p, g_e21);  e21  = (float*)p;
        cudaGetSymbolAddress(&p, g_f0h);  f0h  = (__nv_bfloat16*)p;
        cudaGetSymbolAddress(&p, g_f0l);  f0l  = (__nv_bfloat16*)p;
        cudaGetSymbolAddress(&p, g_f1h);  f1h  = (__nv_bfloat16*)p;
        cudaGetSymbolAddress(&p, g_f1l);  f1l  = (__nv_bfloat16*)p;
        cudaGetSymbolAddress(&p, g_e00h); e00h = (__nv_bfloat16*)p;
        cudaGetSymbolAddress(&p, g_e00l); e00l = (__nv_bfloat16*)p;
        cudaGetSymbolAddress(&p, g_e01h); e01h = (__nv_bfloat16*)p;
        cudaGetSymbolAddress(&p, g_e01l); e01l = (__nv_bfloat16*)p;
        cudaGetSymbolAddress(&p, g_e20h); e20h = (__nv_bfloat16*)p;
        cudaGetSymbolAddress(&p, g_e20l); e20l = (__nv_bfloat16*)p;
        cudaGetSymbolAddress(&p, g_e21h); e21h = (__nv_bfloat16*)p;
        cudaGetSymbolAddress(&p, g_e21l); e21l = (__nv_bfloat16*)p;
        cudaGetSymbolAddress(&p, g_wth);  wth  = (__nv_bfloat16*)p;
        cudaGetSymbolAddress(&p, g_wtl);  wtl  = (__nv_bfloat16*)p;
    }
    float* out = (float*)d_out;

    cudaFuncSetAttribute(gemm_mma, cudaFuncAttributeMaxDynamicSharedMemorySize, GEMM_SMEM);

    auto do_wt = [&](int l, int r) {
        int K = (l == 0) ? KF : KH;
        wt_split<<<dim3(K / 32, KH / 32), dim3(32, 8)>>>(W[l][r], wth + wt_off(l, r),
                                                         wtl + wt_off(l, r), K);
    };
    auto gemm = [&](const __nv_bfloat16* Ah, const __nv_bfloat16* Al,
                    int l, int r, int M, int K) {
        dim3 grid(4, (M + 127) / 128);
        gemm_mma<<<grid, 256, GEMM_SMEM>>>(Ah, Al, wth + wt_off(l, r), wtl + wt_off(l, r),
                                           tmp, M, K);
    };
    auto spmm = [&](int rel, float* dst, int ldo) {
        int E = Ecnt[rel];
        spmm_edges<<<(E + 7) / 8, 256>>>(a_row[rel], a_col[rel], a_val[rel], tmp, dst, E, ldo);
    };
    auto zero = [&](float* p, size_t nelem) {
        size_t n4 = nelem / 4;
        zero_kernel<<<(unsigned)((n4 + 255) / 256), 256>>>(p, n4);
    };

    // Launch order tuned so the 6th launch (ncu -s 5 -c 1) is the big
    // M=30000/K=1024 gemm_mma.
    {
        size_t n4 = (size_t)KN0 * KF / 4;                               // 1
        split_k<<<(unsigned)((n4 + 255) / 256), 256>>>(feat0, f0h, f0l, n4);
        n4 = (size_t)KN1 * KF / 4;                                      // 2
        split_k<<<(unsigned)((n4 + 255) / 256), 256>>>(feat1, f1h, f1l, n4);
    }
    do_wt(0, 0);                                                        // 3
    zero(e00, (size_t)KN0 * KH);                                        // 4
    do_wt(0, 1);                                                        // 5

    // ---------------- Layer 1 (K = F = 1024) ----------------
    gemm(f0h, f0l, 0, 0, KN0, KF);                                      // 6 <- profiled
    spmm(0, e00, KH);
    gemm(f1h, f1l, 0, 1, KN1, KF); spmm(1, e00, KH);
    relu_dual_split<<<(KN0 * 128 + 255) / 256, 256>>>(e00, out, e00h, e00l, KN0);

    do_wt(0, 2); do_wt(0, 3); do_wt(0, 4);
    zero(e01, (size_t)KN1 * KH);
    gemm(f0h, f0l, 0, 2, KN0, KF); spmm(2, e01, KH);
    gemm(f1h, f1l, 0, 3, KN1, KF); spmm(3, e01, KH);
    gemm(f1h, f1l, 0, 4, KN1, KF); spmm(4, e01, KH);
    relu_dual_split<<<(KN1 * 128 + 255) / 256, 256>>>(e01, out + (size_t)KN0 * LDO,
                                                      e01h, e01l, KN1);

    // remaining weight preprocessing
    for (int r = 0; r < 5; r++) { do_wt(1, r); do_wt(2, r); }

    // ---------------- Layer 2 (K = H = 512) ----------------
    zero(e20, (size_t)KN0 * KH);
    gemm(e00h, e00l, 1, 0, KN0, KH); spmm(0, e20, KH);
    gemm(e01h, e01l, 1, 1, KN1, KH); spmm(1, e20, KH);
    relu_split<<<((size_t)KN0 * KH / 4 + 255) / 256, 256>>>(e20, e20h, e20l,
                                                            (size_t)KN0 * KH / 4);

    zero(e21, (size_t)KN1 * KH);
    gemm(e00h, e00l, 1, 2, KN0, KH); spmm(2, e21, KH);
    gemm(e01h, e01l, 1, 3, KN1, KH); spmm(3, e21, KH);
    gemm(e01h, e01l, 1, 4, KN1, KH); spmm(4, e21, KH);
    relu_split<<<((size_t)KN1 * KH / 4 + 255) / 256, 256>>>(e21, e21h, e21l,
                                                            (size_t)KN1 * KH / 4);

    // ---------------- Layer 3 (into d_out cols 1024:1536) ----------------
    zero_cols<<<((KN0 + KN1) * 128 + 255) / 256, 256>>>(out, KN0 + KN1);
    float* out3_t0 = out + 1024;
    float* out3_t1 = out + (size_t)KN0 * LDO + 1024;
    gemm(e20h, e20l, 2, 0, KN0, KH); spmm(0, out3_t0, LDO);
    gemm(e21h, e21l, 2, 1, KN1, KH); spmm(1, out3_t0, LDO);
    gemm(e20h, e20l, 2, 2, KN0, KH); spmm(2, out3_t1, LDO);
    gemm(e21h, e21l, 2, 3, KN1, KH); spmm(3, out3_t1, LDO);
    gemm(e21h, e21l, 2, 4, KN1, KH); spmm(4, out3_t1, LDO);
}

// round 8
// speedup vs baseline: 1.1624x; 1.1624x over previous
#include <cuda_runtime.h>
#include <cuda_bf16.h>
#include <cstdint>
#include <cstddef>

// ============================================================================
// DecagonModel — R8: 1-pass TF32 mma.sync GEMMs (RN-prerounded inputs) + COO
// SpMM via red.global.add.v4.f32.  N0=30000, N1=6000, F=1024, H=512.
// ============================================================================

#define KN0 30000
#define KN1 6000
#define KF  1024
#define KH  512
#define LDO 1536

// ---------------- device-global scratch -------------------------------------
__device__ float g_tmp[KN0 * KH];          // x@W, consumed by SpMM
__device__ float g_e00[KN0 * KH];
__device__ float g_e01[KN1 * KH];
__device__ float g_e20[KN0 * KH];
__device__ float g_e21[KN1 * KH];

// tf32-rounded (RN) GEMM A operands
__device__ float g_f0t[KN0 * KF];
__device__ float g_f1t[KN1 * KF];
__device__ float g_e00t[KN0 * KH];
__device__ float g_e01t[KN1 * KH];
__device__ float g_e20t[KN0 * KH];
__device__ float g_e21t[KN1 * KH];

// transposed tf32-rounded weights [512, K]
#define WT_TOTAL (5 * KH * KF + 10 * KH * KH)
__device__ float g_wt[WT_TOTAL];

// ---------------- helpers ---------------------------------------------------
__device__ __forceinline__ uint32_t smem_u32(const void* p) {
    uint32_t a;
    asm("{ .reg .u64 t; cvta.to.shared.u64 t, %1; cvt.u32.u64 %0, t; }"
        : "=r"(a) : "l"(p));
    return a;
}
__device__ __forceinline__ void cpa16(uint32_t dst, const void* src, bool v) {
    asm volatile("cp.async.cg.shared.global [%0], [%1], 16, %2;"
                 :: "r"(dst), "l"(src), "r"(v ? 16 : 0) : "memory");
}
__device__ __forceinline__ void ldsm4(uint32_t& r0, uint32_t& r1, uint32_t& r2,
                                      uint32_t& r3, uint32_t addr) {
    asm volatile("ldmatrix.sync.aligned.m8n8.x4.shared.b16 {%0,%1,%2,%3}, [%4];"
                 : "=r"(r0), "=r"(r1), "=r"(r2), "=r"(r3) : "r"(addr));
}
// m16n8k8 tf32 mma, fp32 accumulate
__device__ __forceinline__ void mma_tf32(float& c0, float& c1, float& c2, float& c3,
                                         uint32_t a0, uint32_t a1, uint32_t a2, uint32_t a3,
                                         uint32_t b0, uint32_t b1) {
    asm volatile(
        "mma.sync.aligned.m16n8k8.row.col.f32.tf32.tf32.f32 "
        "{%0,%1,%2,%3}, {%4,%5,%6,%7}, {%8,%9}, {%0,%1,%2,%3};"
        : "+f"(c0), "+f"(c1), "+f"(c2), "+f"(c3)
        : "r"(a0), "r"(a1), "r"(a2), "r"(a3), "r"(b0), "r"(b1));
}
__device__ __forceinline__ float tf32r(float x) {
    uint32_t r;
    asm("cvt.rna.tf32.f32 %0, %1;" : "=r"(r) : "f"(x));
    return __uint_as_float(r);
}
// smem rows: 32 fp32 = 128B; XOR swizzle on 16B granules (g' = g ^ (r&7)):
// conflict-free for cp.async 16B stores and ldmatrix reads.
__device__ __forceinline__ uint32_t swz128(int r, int cbyte) {
    return (uint32_t)(r * 128 + (cbyte ^ (((r) & 7) << 4)));
}

// ----------------------------------------------------------------------------
// GEMM: C[M,512] = A[M,K] @ B^T, A,B fp32 (tf32-prerounded), B stored [512,K].
// CTA 128x128, BK=32 (fp32), 3-stage cp.async, 256 threads, warp tile 64x32.
// ----------------------------------------------------------------------------
#define STG_BYTES 32768u        // A 16K | B 16K
#define GEMM_SMEM (3 * STG_BYTES)

__global__ __launch_bounds__(256) void gemm_tf32(
    const float* __restrict__ A, const float* __restrict__ B,
    float* __restrict__ C, int M, int K)
{
    extern __shared__ char dyn_smem[];
    const uint32_t sbase = smem_u32(dyn_smem);

    const int tid  = threadIdx.x;
    const int wid  = tid >> 5;
    const int lane = tid & 31;
    const int bm   = blockIdx.y * 128;
    const int bn   = blockIdx.x * 128;
    const int wm   = (wid & 1) * 64;
    const int wn   = (wid >> 1) * 32;

    const int NC = K >> 5;      // 32-fp32-wide K chunks

    // 2048 16B granules per stage (A 1024 + B 1024); 8 per thread
    auto load_stage = [&](int c) {
        const uint32_t st = sbase + (uint32_t)(c % 3) * STG_BYTES;
        const int k0 = c << 5;
#pragma unroll
        for (int it = 0; it < 8; it++) {
            int seg  = it * 256 + tid;
            int half = seg >> 10;            // 0 = A, 1 = B
            int r    = (seg >> 3) & 127;
            int cs   = seg & 7;              // 16B granule in 128B row
            uint32_t dst = st + (uint32_t)half * 16384u + swz128(r, cs * 16);
            const float* src;
            bool v = true;
            if (half == 0) {
                int gr = bm + r;
                v = gr < M; if (!v) gr = 0;
                src = A + (size_t)gr * K + k0 + cs * 4;
            } else {
                src = B + (size_t)(bn + r) * K + k0 + cs * 4;
            }
            cpa16(dst, src, v);
        }
        asm volatile("cp.async.commit_group;" ::: "memory");
    };

    float acc[4][4][4];
#pragma unroll
    for (int i = 0; i < 4; i++)
#pragma unroll
        for (int j = 0; j < 4; j++)
#pragma unroll
            for (int q = 0; q < 4; q++) acc[i][j][q] = 0.f;

    load_stage(0);
    load_stage(1);

    // ldmatrix lane addressing (8x4-fp32 blocks; same pattern for A and B)
    const int mi  = lane >> 3;           // matrix index this lane addresses
    const int r8  = lane & 7;
    const int aro = (mi & 1) * 8 + r8;   // row within 16-row tile
    const int akb = (mi >> 1) * 16;      // 16B granule: k 0-3 vs 4-7

    for (int c = 0; c < NC; c++) {
        asm volatile("cp.async.wait_group 1;" ::: "memory");
        __syncthreads();
        if (c + 2 < NC) load_stage(c + 2);

        const uint32_t st = sbase + (uint32_t)(c % 3) * STG_BYTES;
        const uint32_t sA = st, sB = st + 16384;

#pragma unroll
        for (int s = 0; s < 4; s++) {           // four k8 steps
            const int kb = s * 32;              // byte offset of k8 group
            uint32_t a[4][4], bf[4][2];
            // A: 4 m16 tiles; ldmatrix.x4 -> a0..a3 exactly (tf32 frag layout)
            #pragma unroll
            for (int i = 0; i < 4; i++)
                ldsm4(a[i][0], a[i][1], a[i][2], a[i][3],
                      sA + swz128(wm + i * 16 + aro, kb + akb));
            // B: 2 x4 loads cover n32 x k8; frag per n8 = {klo, khi}
            #pragma unroll
            for (int j2 = 0; j2 < 2; j2++) {
                uint32_t r0, r1, r2, r3;
                ldsm4(r0, r1, r2, r3, sB + swz128(wn + j2 * 16 + aro, kb + akb));
                bf[j2 * 2][0]     = r0; bf[j2 * 2][1]     = r2;
                bf[j2 * 2 + 1][0] = r1; bf[j2 * 2 + 1][1] = r3;
            }
            #pragma unroll
            for (int i = 0; i < 4; i++)
                #pragma unroll
                for (int j = 0; j < 4; j++)
                    mma_tf32(acc[i][j][0], acc[i][j][1], acc[i][j][2], acc[i][j][3],
                             a[i][0], a[i][1], a[i][2], a[i][3],
                             bf[j][0], bf[j][1]);
        }
        __syncthreads();
    }

    const int lm = lane >> 2, ln = (lane & 3) * 2;
#pragma unroll
    for (int i = 0; i < 4; i++) {
#pragma unroll
        for (int j = 0; j < 4; j++) {
            int m0 = bm + wm + i * 16 + lm;
            int n0 = bn + wn + j * 8 + ln;
            if (m0 < M)
                *(float2*)(C + (size_t)m0 * KH + n0) =
                    make_float2(acc[i][j][0], acc[i][j][1]);
            if (m0 + 8 < M)
                *(float2*)(C + (size_t)(m0 + 8) * KH + n0) =
                    make_float2(acc[i][j][2], acc[i][j][3]);
        }
    }
}

// ----------------------------------------------------------------------------
// SpMM (COO, warp/edge) with red.global.add.v4.f32
// ----------------------------------------------------------------------------
__global__ __launch_bounds__(256) void spmm_edges(
    const int* __restrict__ row, const int* __restrict__ col,
    const float* __restrict__ val, const float* __restrict__ x,
    float* __restrict__ out, int E, int ldo)
{
    int warp = (blockIdx.x * blockDim.x + threadIdx.x) >> 5;
    int lane = threadIdx.x & 31;
    if (warp >= E) return;
    const int   r = row[warp];
    const int   c = col[warp];
    const float v = val[warp];
    const float4* xr   = reinterpret_cast<const float4*>(x + (size_t)c * KH);
    float*        orow = out + (size_t)r * ldo;
#pragma unroll
    for (int i = 0; i < 4; i++) {
        float4 t = xr[lane + i * 32];
        float* p = orow + (size_t)(lane + i * 32) * 4;
        asm volatile("red.global.add.v4.f32 [%0], {%1, %2, %3, %4};"
                     :: "l"(p), "f"(t.x * v), "f"(t.y * v), "f"(t.z * v), "f"(t.w * v)
                     : "memory");
    }
}

// ----------------------------------------------------------------------------
// Converters / epilogues
// ----------------------------------------------------------------------------
__global__ void tf32_round4(const float* __restrict__ x, float* __restrict__ y, size_t n4)
{
    size_t i = blockIdx.x * (size_t)blockDim.x + threadIdx.x;
    if (i >= n4) return;
    float4 t = reinterpret_cast<const float4*>(x)[i];
    t.x = tf32r(t.x); t.y = tf32r(t.y); t.z = tf32r(t.z); t.w = tf32r(t.w);
    reinterpret_cast<float4*>(y)[i] = t;
}

// W [K,512] f32 -> Wt [512,K] tf32-rounded f32
__global__ void wt_t(const float* __restrict__ W, float* __restrict__ T, int K)
{
    __shared__ float t[32][33];
    int kb = blockIdx.x * 32, nb = blockIdx.y * 32;
    int x = threadIdx.x, y = threadIdx.y;   // block (32,8)
#pragma unroll
    for (int i = 0; i < 32; i += 8)
        t[y + i][x] = W[(size_t)(kb + y + i) * KH + nb + x];
    __syncthreads();
#pragma unroll
    for (int i = 0; i < 32; i += 8)
        T[(size_t)(nb + y + i) * K + kb + x] = tf32r(t[x][y + i]);
}

__global__ void zero_kernel(float* __restrict__ p, size_t n4)
{
    size_t i = blockIdx.x * (size_t)blockDim.x + threadIdx.x;
    if (i < n4) reinterpret_cast<float4*>(p)[i] = make_float4(0.f, 0.f, 0.f, 0.f);
}

__global__ void zero_cols(float* __restrict__ out, int nrows)
{
    int idx = blockIdx.x * blockDim.x + threadIdx.x;
    if (idx >= nrows * 128) return;
    int r = idx >> 7, c = idx & 127;
    reinterpret_cast<float4*>(out + (size_t)r * LDO + 1024)[c] =
        make_float4(0.f, 0.f, 0.f, 0.f);
}

// relu(e): write dual exact copies to d_out + tf32-rounded copy for next gemm
__global__ void relu_dual_t(const float* __restrict__ e, float* __restrict__ outbase,
                            float* __restrict__ et, int n)
{
    int idx = blockIdx.x * blockDim.x + threadIdx.x;
    if (idx >= n * 128) return;
    float4 t = reinterpret_cast<const float4*>(e)[idx];
    t.x = fmaxf(t.x, 0.f); t.y = fmaxf(t.y, 0.f);
    t.z = fmaxf(t.z, 0.f); t.w = fmaxf(t.w, 0.f);
    int r = idx >> 7, c = idx & 127;
    float4* o = reinterpret_cast<float4*>(outbase + (size_t)r * LDO);
    o[c]       = t;
    o[c + 128] = t;
    t.x = tf32r(t.x); t.y = tf32r(t.y); t.z = tf32r(t.z); t.w = tf32r(t.w);
    reinterpret_cast<float4*>(et)[idx] = t;
}

// relu + tf32 round only (layer-2 embeddings; exact copy not needed downstream)
__global__ void relu_t(const float* __restrict__ e, float* __restrict__ et, size_t n4)
{
    size_t i = blockIdx.x * (size_t)blockDim.x + threadIdx.x;
    if (i >= n4) return;
    float4 t = reinterpret_cast<const float4*>(e)[i];
    t.x = tf32r(fmaxf(t.x, 0.f)); t.y = tf32r(fmaxf(t.y, 0.f));
    t.z = tf32r(fmaxf(t.z, 0.f)); t.w = tf32r(fmaxf(t.w, 0.f));
    reinterpret_cast<float4*>(et)[i] = t;
}

// ----------------------------------------------------------------------------
// Host orchestration
// ----------------------------------------------------------------------------
static size_t wt_off(int l, int r)
{
    if (l == 0) return (size_t)r * KH * KF;
    return (size_t)5 * KH * KF + (size_t)((l - 1) * 5 + r) * KH * KH;
}

extern "C" void kernel_launch(void* const* d_in, const int* in_sizes, int n_in,
                              void* d_out, int out_size)
{
    const float* feat0 = (const float*)d_in[0];
    const float* feat1 = (const float*)d_in[1];

    const int*   a_row[5]; const int* a_col[5]; const float* a_val[5]; int Ecnt[5];
    for (int i = 0; i < 5; i++) {
        a_row[i] = (const int*)d_in[2 + 3 * i];
        a_col[i] = (const int*)d_in[3 + 3 * i];
        a_val[i] = (const float*)d_in[4 + 3 * i];
        Ecnt[i]  = in_sizes[2 + 3 * i];
    }
    const float* W[3][5];
    for (int r = 0; r < 5; r++)
        for (int l = 0; l < 3; l++)
            W[l][r] = (const float*)d_in[17 + 3 * r + l];

    float *tmp, *e00, *e01, *e20, *e21;
    float *f0t, *f1t, *e00t, *e01t, *e20t, *e21t, *wt;
    {
        void* p;
        cudaGetSymbolAddress(&p, g_tmp);  tmp  = (float*)p;
        cudaGetSymbolAddress(&p, g_e00);  e00  = (float*)p;
        cudaGetSymbolAddress(&p, g_e01);  e01  = (float*)p;
        cudaGetSymbolAddress(&p, g_e20);  e20  = (float*)p;
        cudaGetSymbolAddress(&p, g_e21);  e21  = (float*)p;
        cudaGetSymbolAddress(&p, g_f0t);  f0t  = (float*)p;
        cudaGetSymbolAddress(&p, g_f1t);  f1t  = (float*)p;
        cudaGetSymbolAddress(&p, g_e00t); e00t = (float*)p;
        cudaGetSymbolAddress(&p, g_e01t); e01t = (float*)p;
        cudaGetSymbolAddress(&p, g_e20t); e20t = (float*)p;
        cudaGetSymbolAddress(&p, g_e21t); e21t = (float*)p;
        cudaGetSymbolAddress(&p, g_wt);   wt   = (float*)p;
    }
    float* out = (float*)d_out;

    cudaFuncSetAttribute(gemm_tf32, cudaFuncAttributeMaxDynamicSharedMemorySize, GEMM_SMEM);

    auto do_wt = [&](int l, int r) {
        int K = (l == 0) ? KF : KH;
        wt_t<<<dim3(K / 32, KH / 32), dim3(32, 8)>>>(W[l][r], wt + wt_off(l, r), K);
    };
    auto gemm = [&](const float* A, int l, int r, int M, int K) {
        dim3 grid(4, (M + 127) / 128);
        gemm_tf32<<<grid, 256, GEMM_SMEM>>>(A, wt + wt_off(l, r), tmp, M, K);
    };
    auto spmm = [&](int rel, float* dst, int ldo) {
        int E = Ecnt[rel];
        spmm_edges<<<(E + 7) / 8, 256>>>(a_row[rel], a_col[rel], a_val[rel], tmp, dst, E, ldo);
    };
    auto zero = [&](float* p, size_t nelem) {
        size_t n4 = nelem / 4;
        zero_kernel<<<(unsigned)((n4 + 255) / 256), 256>>>(p, n4);
    };
    auto round_to = [&](const float* s, float* d, size_t nelem) {
        size_t n4 = nelem / 4;
        tf32_round4<<<(unsigned)((n4 + 255) / 256), 256>>>(s, d, n4);
    };

    // Launch order: #4 is the big M=30000/K=1024 gemm (empirically ncu
    // profiles the 4th launch).
    do_wt(0, 0);                                      // 1
    round_to(feat0, f0t, (size_t)KN0 * KF);           // 2
    zero(e00, (size_t)KN0 * KH);                      // 3
    gemm(f0t, 0, 0, KN0, KF);                         // 4  <- profiled
    spmm(0, e00, KH);                                 // 5
    round_to(feat1, f1t, (size_t)KN1 * KF);           // 6
    do_wt(0, 1);
    gemm(f1t, 0, 1, KN1, KF); spmm(1, e00, KH);
    relu_dual_t<<<(KN0 * 128 + 255) / 256, 256>>>(e00, out, e00t, KN0);

    do_wt(0, 2); do_wt(0, 3); do_wt(0, 4);
    zero(e01, (size_t)KN1 * KH);
    gemm(f0t, 0, 2, KN0, KF); spmm(2, e01, KH);
    gemm(f1t, 0, 3, KN1, KF); spmm(3, e01, KH);
    gemm(f1t, 0, 4, KN1, KF); spmm(4, e01, KH);
    relu_dual_t<<<(KN1 * 128 + 255) / 256, 256>>>(e01, out + (size_t)KN0 * LDO, e01t, KN1);

    for (int r = 0; r < 5; r++) { do_wt(1, r); do_wt(2, r); }

    // ---------------- Layer 2 (K = H = 512) ----------------
    zero(e20, (size_t)KN0 * KH);
    gemm(e00t, 1, 0, KN0, KH); spmm(0, e20, KH);
    gemm(e01t, 1, 1, KN1, KH); spmm(1, e20, KH);
    relu_t<<<((size_t)KN0 * KH / 4 + 255) / 256, 256>>>(e20, e20t, (size_t)KN0 * KH / 4);

    zero(e21, (size_t)KN1 * KH);
    gemm(e00t, 1, 2, KN0, KH); spmm(2, e21, KH);
    gemm(e01t, 1, 3, KN1, KH); spmm(3, e21, KH);
    gemm(e01t, 1, 4, KN1, KH); spmm(4, e21, KH);
    relu_t<<<((size_t)KN1 * KH / 4 + 255) / 256, 256>>>(e21, e21t, (size_t)KN1 * KH / 4);

    // ---------------- Layer 3 (into d_out cols 1024:1536) ----------------
    zero_cols<<<((KN0 + KN1) * 128 + 255) / 256, 256>>>(out, KN0 + KN1);
    float* out3_t0 = out + 1024;
    float* out3_t1 = out + (size_t)KN0 * LDO + 1024;
    gemm(e20t, 2, 0, KN0, KH); spmm(0, out3_t0, LDO);
    gemm(e21t, 2, 1, KN1, KH); spmm(1, out3_t0, LDO);
    gemm(e20t, 2, 2, KN0, KH); spmm(2, out3_t1, LDO);
    gemm(e21t, 2, 3, KN1, KH); spmm(3, out3_t1, LDO);
    gemm(e21t, 2, 4, KN1, KH); spmm(4, out3_t1, LDO);
}

// round 9
// speedup vs baseline: 1.7208x; 1.4804x over previous
#include <cuda_runtime.h>
#include <cuda_bf16.h>
#include <cstdint>
#include <cstddef>

// ============================================================================
// DecagonModel — R9: TF32 mma GEMMs + CSR SpMM (warp/row, write-once).
// N0=30000, N1=6000, F=1024, H=512, out [36000, 1536] f32.
// ============================================================================

#define KN0 30000
#define KN1 6000
#define KF  1024
#define KH  512
#define LDO 1536
#define ECAP 2100000
#define RPN  30001          // rowptr slots per relation (max N0+1)

// ---------------- device-global scratch -------------------------------------
__device__ float g_tmp[KN0 * KH];
__device__ float g_e00[KN0 * KH];
__device__ float g_e01[KN1 * KH];
__device__ float g_e20[KN0 * KH];
__device__ float g_e21[KN1 * KH];

__device__ float g_f0t[KN0 * KF];
__device__ float g_f1t[KN1 * KF];
__device__ float g_e00t[KN0 * KH];
__device__ float g_e01t[KN1 * KH];
__device__ float g_e20t[KN0 * KH];
__device__ float g_e21t[KN1 * KH];

#define WT_TOTAL (5 * KH * KF + 10 * KH * KH)
__device__ float g_wt[WT_TOTAL];

// CSR storage
__device__ int   g_rp[5 * RPN];
__device__ int   g_wp[5 * RPN];
__device__ int   g_colv[ECAP];
__device__ float g_valv[ECAP];

// ---------------- helpers ---------------------------------------------------
__device__ __forceinline__ uint32_t smem_u32(const void* p) {
    uint32_t a;
    asm("{ .reg .u64 t; cvta.to.shared.u64 t, %1; cvt.u32.u64 %0, t; }"
        : "=r"(a) : "l"(p));
    return a;
}
__device__ __forceinline__ void cpa16(uint32_t dst, const void* src, bool v) {
    asm volatile("cp.async.cg.shared.global [%0], [%1], 16, %2;"
                 :: "r"(dst), "l"(src), "r"(v ? 16 : 0) : "memory");
}
__device__ __forceinline__ void ldsm4(uint32_t& r0, uint32_t& r1, uint32_t& r2,
                                      uint32_t& r3, uint32_t addr) {
    asm volatile("ldmatrix.sync.aligned.m8n8.x4.shared.b16 {%0,%1,%2,%3}, [%4];"
                 : "=r"(r0), "=r"(r1), "=r"(r2), "=r"(r3) : "r"(addr));
}
__device__ __forceinline__ void mma_tf32(float& c0, float& c1, float& c2, float& c3,
                                         uint32_t a0, uint32_t a1, uint32_t a2, uint32_t a3,
                                         uint32_t b0, uint32_t b1) {
    asm volatile(
        "mma.sync.aligned.m16n8k8.row.col.f32.tf32.tf32.f32 "
        "{%0,%1,%2,%3}, {%4,%5,%6,%7}, {%8,%9}, {%0,%1,%2,%3};"
        : "+f"(c0), "+f"(c1), "+f"(c2), "+f"(c3)
        : "r"(a0), "r"(a1), "r"(a2), "r"(a3), "r"(b0), "r"(b1));
}
__device__ __forceinline__ float tf32r(float x) {
    uint32_t r;
    asm("cvt.rna.tf32.f32 %0, %1;" : "=r"(r) : "f"(x));
    return __uint_as_float(r);
}
__device__ __forceinline__ uint32_t swz128(int r, int cbyte) {
    return (uint32_t)(r * 128 + (cbyte ^ (((r) & 7) << 4)));
}

// ----------------------------------------------------------------------------
// TF32 GEMM (unchanged from R8): C[M,512] = A[M,K] @ B^T, B stored [512,K].
// ----------------------------------------------------------------------------
#define STG_BYTES 32768u
#define GEMM_SMEM (3 * STG_BYTES)

__global__ __launch_bounds__(256) void gemm_tf32(
    const float* __restrict__ A, const float* __restrict__ B,
    float* __restrict__ C, int M, int K)
{
    extern __shared__ char dyn_smem[];
    const uint32_t sbase = smem_u32(dyn_smem);

    const int tid  = threadIdx.x;
    const int wid  = tid >> 5;
    const int lane = tid & 31;
    const int bm   = blockIdx.y * 128;
    const int bn   = blockIdx.x * 128;
    const int wm   = (wid & 1) * 64;
    const int wn   = (wid >> 1) * 32;

    const int NC = K >> 5;

    auto load_stage = [&](int c) {
        const uint32_t st = sbase + (uint32_t)(c % 3) * STG_BYTES;
        const int k0 = c << 5;
#pragma unroll
        for (int it = 0; it < 8; it++) {
            int seg  = it * 256 + tid;
            int half = seg >> 10;
            int r    = (seg >> 3) & 127;
            int cs   = seg & 7;
            uint32_t dst = st + (uint32_t)half * 16384u + swz128(r, cs * 16);
            const float* src;
            bool v = true;
            if (half == 0) {
                int gr = bm + r;
                v = gr < M; if (!v) gr = 0;
                src = A + (size_t)gr * K + k0 + cs * 4;
            } else {
                src = B + (size_t)(bn + r) * K + k0 + cs * 4;
            }
            cpa16(dst, src, v);
        }
        asm volatile("cp.async.commit_group;" ::: "memory");
    };

    float acc[4][4][4];
#pragma unroll
    for (int i = 0; i < 4; i++)
#pragma unroll
        for (int j = 0; j < 4; j++)
#pragma unroll
            for (int q = 0; q < 4; q++) acc[i][j][q] = 0.f;

    load_stage(0);
    load_stage(1);

    const int mi  = lane >> 3;
    const int r8  = lane & 7;
    const int aro = (mi & 1) * 8 + r8;
    const int akb = (mi >> 1) * 16;

    for (int c = 0; c < NC; c++) {
        asm volatile("cp.async.wait_group 1;" ::: "memory");
        __syncthreads();
        if (c + 2 < NC) load_stage(c + 2);

        const uint32_t st = sbase + (uint32_t)(c % 3) * STG_BYTES;
        const uint32_t sA = st, sB = st + 16384;

#pragma unroll
        for (int s = 0; s < 4; s++) {
            const int kb = s * 32;
            uint32_t a[4][4], bf[4][2];
            #pragma unroll
            for (int i = 0; i < 4; i++)
                ldsm4(a[i][0], a[i][1], a[i][2], a[i][3],
                      sA + swz128(wm + i * 16 + aro, kb + akb));
            #pragma unroll
            for (int j2 = 0; j2 < 2; j2++) {
                uint32_t r0, r1, r2, r3;
                ldsm4(r0, r1, r2, r3, sB + swz128(wn + j2 * 16 + aro, kb + akb));
                bf[j2 * 2][0]     = r0; bf[j2 * 2][1]     = r2;
                bf[j2 * 2 + 1][0] = r1; bf[j2 * 2 + 1][1] = r3;
            }
            #pragma unroll
            for (int i = 0; i < 4; i++)
                #pragma unroll
                for (int j = 0; j < 4; j++)
                    mma_tf32(acc[i][j][0], acc[i][j][1], acc[i][j][2], acc[i][j][3],
                             a[i][0], a[i][1], a[i][2], a[i][3],
                             bf[j][0], bf[j][1]);
        }
        __syncthreads();
    }

    const int lm = lane >> 2, ln = (lane & 3) * 2;
#pragma unroll
    for (int i = 0; i < 4; i++) {
#pragma unroll
        for (int j = 0; j < 4; j++) {
            int m0 = bm + wm + i * 16 + lm;
            int n0 = bn + wn + j * 8 + ln;
            if (m0 < M)
                *(float2*)(C + (size_t)m0 * KH + n0) =
                    make_float2(acc[i][j][0], acc[i][j][1]);
            if (m0 + 8 < M)
                *(float2*)(C + (size_t)(m0 + 8) * KH + n0) =
                    make_float2(acc[i][j][2], acc[i][j][3]);
        }
    }
}

// ----------------------------------------------------------------------------
// CSR build kernels
// ----------------------------------------------------------------------------
__global__ void seti(int* __restrict__ p, int n, int v)
{
    int i = blockIdx.x * blockDim.x + threadIdx.x;
    if (i < n) p[i] = v;
}
__global__ void hist(const int* __restrict__ row, int E, int* __restrict__ cnt)
{
    int i = blockIdx.x * blockDim.x + threadIdx.x;
    if (i < E) atomicAdd(&cnt[row[i]], 1);
}
// single-block exclusive scan: rp[i] = sum(cnt[0..i)), i in [0, n]
__global__ void exscan(const int* __restrict__ cnt, int* __restrict__ rp, int n)
{
    __shared__ int part[1024];
    const int t = threadIdx.x;
    const int chunk = (n + 1 + 1023) / 1024;
    const int base = t * chunk;
    int s = 0;
    for (int i = 0; i < chunk; i++) {
        int idx = base + i;
        if (idx < n) s += cnt[idx];
    }
    part[t] = s;
    __syncthreads();
    for (int off = 1; off < 1024; off <<= 1) {
        int v = (t >= off) ? part[t - off] : 0;
        __syncthreads();
        part[t] += v;
        __syncthreads();
    }
    int run = part[t] - s;              // exclusive prefix of this chunk
    for (int i = 0; i < chunk; i++) {
        int idx = base + i;
        if (idx <= n) {
            rp[idx] = run;
            if (idx < n) run += cnt[idx];
        }
    }
}
__global__ void copyi(const int* __restrict__ s, int* __restrict__ d, int n)
{
    int i = blockIdx.x * blockDim.x + threadIdx.x;
    if (i < n) d[i] = s[i];
}
__global__ void scatter(const int* __restrict__ row, const int* __restrict__ col,
                        const float* __restrict__ val, int E,
                        int* __restrict__ wp, int* __restrict__ colv,
                        float* __restrict__ valv)
{
    int i = blockIdx.x * blockDim.x + threadIdx.x;
    if (i >= E) return;
    int p = atomicAdd(&wp[row[i]], 1);
    colv[p] = col[i];
    valv[p] = val[i];
}

// ----------------------------------------------------------------------------
// CSR SpMM: warp per output row; acc in registers; single write.
// beta=0: out_row = acc (covers zero-degree rows; replaces zero kernels)
// beta=1: out_row += acc
// ----------------------------------------------------------------------------
__global__ __launch_bounds__(256) void spmm_csr(
    const int* __restrict__ rp, const int* __restrict__ colv,
    const float* __restrict__ valv, const float* __restrict__ x,
    float* __restrict__ out, int nrows, int ldo, int beta)
{
    int row  = (blockIdx.x * blockDim.x + threadIdx.x) >> 5;
    int lane = threadIdx.x & 31;
    if (row >= nrows) return;
    int s = rp[row], e = rp[row + 1];

    float4 a0 = make_float4(0.f, 0.f, 0.f, 0.f), a1 = a0, a2 = a0, a3 = a0;

#pragma unroll 2
    for (int i = s; i < e; i++) {
        int   c = __ldg(&colv[i]);
        float v = __ldg(&valv[i]);
        const float4* xr = reinterpret_cast<const float4*>(x + (size_t)c * KH);
        float4 t;
        t = xr[lane];
        a0.x = fmaf(v, t.x, a0.x); a0.y = fmaf(v, t.y, a0.y);
        a0.z = fmaf(v, t.z, a0.z); a0.w = fmaf(v, t.w, a0.w);
        t = xr[lane + 32];
        a1.x = fmaf(v, t.x, a1.x); a1.y = fmaf(v, t.y, a1.y);
        a1.z = fmaf(v, t.z, a1.z); a1.w = fmaf(v, t.w, a1.w);
        t = xr[lane + 64];
        a2.x = fmaf(v, t.x, a2.x); a2.y = fmaf(v, t.y, a2.y);
        a2.z = fmaf(v, t.z, a2.z); a2.w = fmaf(v, t.w, a2.w);
        t = xr[lane + 96];
        a3.x = fmaf(v, t.x, a3.x); a3.y = fmaf(v, t.y, a3.y);
        a3.z = fmaf(v, t.z, a3.z); a3.w = fmaf(v, t.w, a3.w);
    }

    float4* o = reinterpret_cast<float4*>(out + (size_t)row * ldo);
    if (beta) {
        float4 t;
        t = o[lane];      a0.x += t.x; a0.y += t.y; a0.z += t.z; a0.w += t.w;
        t = o[lane + 32]; a1.x += t.x; a1.y += t.y; a1.z += t.z; a1.w += t.w;
        t = o[lane + 64]; a2.x += t.x; a2.y += t.y; a2.z += t.z; a2.w += t.w;
        t = o[lane + 96]; a3.x += t.x; a3.y += t.y; a3.z += t.z; a3.w += t.w;
    }
    o[lane]      = a0;
    o[lane + 32] = a1;
    o[lane + 64] = a2;
    o[lane + 96] = a3;
}

// ----------------------------------------------------------------------------
// Converters / epilogues
// ----------------------------------------------------------------------------
__global__ void tf32_round4(const float* __restrict__ x, float* __restrict__ y, size_t n4)
{
    size_t i = blockIdx.x * (size_t)blockDim.x + threadIdx.x;
    if (i >= n4) return;
    float4 t = reinterpret_cast<const float4*>(x)[i];
    t.x = tf32r(t.x); t.y = tf32r(t.y); t.z = tf32r(t.z); t.w = tf32r(t.w);
    reinterpret_cast<float4*>(y)[i] = t;
}

__global__ void wt_t(const float* __restrict__ W, float* __restrict__ T, int K)
{
    __shared__ float t[32][33];
    int kb = blockIdx.x * 32, nb = blockIdx.y * 32;
    int x = threadIdx.x, y = threadIdx.y;
#pragma unroll
    for (int i = 0; i < 32; i += 8)
        t[y + i][x] = W[(size_t)(kb + y + i) * KH + nb + x];
    __syncthreads();
#pragma unroll
    for (int i = 0; i < 32; i += 8)
        T[(size_t)(nb + y + i) * K + kb + x] = tf32r(t[x][y + i]);
}

__global__ void relu_dual_t(const float* __restrict__ e, float* __restrict__ outbase,
                            float* __restrict__ et, int n)
{
    int idx = blockIdx.x * blockDim.x + threadIdx.x;
    if (idx >= n * 128) return;
    float4 t = reinterpret_cast<const float4*>(e)[idx];
    t.x = fmaxf(t.x, 0.f); t.y = fmaxf(t.y, 0.f);
    t.z = fmaxf(t.z, 0.f); t.w = fmaxf(t.w, 0.f);
    int r = idx >> 7, c = idx & 127;
    float4* o = reinterpret_cast<float4*>(outbase + (size_t)r * LDO);
    o[c]       = t;
    o[c + 128] = t;
    t.x = tf32r(t.x); t.y = tf32r(t.y); t.z = tf32r(t.z); t.w = tf32r(t.w);
    reinterpret_cast<float4*>(et)[idx] = t;
}

__global__ void relu_t(const float* __restrict__ e, float* __restrict__ et, size_t n4)
{
    size_t i = blockIdx.x * (size_t)blockDim.x + threadIdx.x;
    if (i >= n4) return;
    float4 t = reinterpret_cast<const float4*>(e)[i];
    t.x = tf32r(fmaxf(t.x, 0.f)); t.y = tf32r(fmaxf(t.y, 0.f));
    t.z = tf32r(fmaxf(t.z, 0.f)); t.w = tf32r(fmaxf(t.w, 0.f));
    reinterpret_cast<float4*>(et)[i] = t;
}

// ----------------------------------------------------------------------------
// Host orchestration
// ----------------------------------------------------------------------------
static size_t wt_off(int l, int r)
{
    if (l == 0) return (size_t)r * KH * KF;
    return (size_t)5 * KH * KF + (size_t)((l - 1) * 5 + r) * KH * KH;
}

extern "C" void kernel_launch(void* const* d_in, const int* in_sizes, int n_in,
                              void* d_out, int out_size)
{
    const float* feat0 = (const float*)d_in[0];
    const float* feat1 = (const float*)d_in[1];

    const int*   a_row[5]; const int* a_col[5]; const float* a_val[5]; int Ecnt[5];
    for (int i = 0; i < 5; i++) {
        a_row[i] = (const int*)d_in[2 + 3 * i];
        a_col[i] = (const int*)d_in[3 + 3 * i];
        a_val[i] = (const float*)d_in[4 + 3 * i];
        Ecnt[i]  = in_sizes[2 + 3 * i];
    }
    const int nrows_rel[5] = {KN0, KN0, KN1, KN1, KN1};
    const float* W[3][5];
    for (int r = 0; r < 5; r++)
        for (int l = 0; l < 3; l++)
            W[l][r] = (const float*)d_in[17 + 3 * r + l];

    float *tmp, *e00, *e01, *e20, *e21;
    float *f0t, *f1t, *e00t, *e01t, *e20t, *e21t, *wt;
    int *rp, *wp, *colv; float *valv;
    {
        void* p;
        cudaGetSymbolAddress(&p, g_tmp);  tmp  = (float*)p;
        cudaGetSymbolAddress(&p, g_e00);  e00  = (float*)p;
        cudaGetSymbolAddress(&p, g_e01);  e01  = (float*)p;
        cudaGetSymbolAddress(&p, g_e20);  e20  = (float*)p;
        cudaGetSymbolAddress(&p, g_e21);  e21  = (float*)p;
        cudaGetSymbolAddress(&p, g_f0t);  f0t  = (float*)p;
        cudaGetSymbolAddress(&p, g_f1t);  f1t  = (float*)p;
        cudaGetSymbolAddress(&p, g_e00t); e00t = (float*)p;
        cudaGetSymbolAddress(&p, g_e01t); e01t = (float*)p;
        cudaGetSymbolAddress(&p, g_e20t); e20t = (float*)p;
        cudaGetSymbolAddress(&p, g_e21t); e21t = (float*)p;
        cudaGetSymbolAddress(&p, g_wt);   wt   = (float*)p;
        cudaGetSymbolAddress(&p, g_rp);   rp   = (int*)p;
        cudaGetSymbolAddress(&p, g_wp);   wp   = (int*)p;
        cudaGetSymbolAddress(&p, g_colv); colv = (int*)p;
        cudaGetSymbolAddress(&p, g_valv); valv = (float*)p;
    }
    float* out = (float*)d_out;

    // edge-array offsets per relation
    size_t eoff[5]; size_t acc_e = 0;
    for (int r = 0; r < 5; r++) { eoff[r] = acc_e; acc_e += (size_t)Ecnt[r]; }

    cudaFuncSetAttribute(gemm_tf32, cudaFuncAttributeMaxDynamicSharedMemorySize, GEMM_SMEM);

    auto do_wt = [&](int l, int r) {
        int K = (l == 0) ? KF : KH;
        wt_t<<<dim3(K / 32, KH / 32), dim3(32, 8)>>>(W[l][r], wt + wt_off(l, r), K);
    };
    auto gemm = [&](const float* A, int l, int r, int M, int K) {
        dim3 grid(4, (M + 127) / 128);
        gemm_tf32<<<grid, 256, GEMM_SMEM>>>(A, wt + wt_off(l, r), tmp, M, K);
    };
    auto build_csr = [&](int r) {
        int n = nrows_rel[r], E = Ecnt[r];
        int* rpr = rp + r * RPN;
        int* wpr = wp + r * RPN;
        seti<<<(n + 255) / 256, 256>>>(wpr, n, 0);
        hist<<<(E + 255) / 256, 256>>>(a_row[r], E, wpr);
        exscan<<<1, 1024>>>(wpr, rpr, n);
        copyi<<<(n + 255) / 256, 256>>>(rpr, wpr, n);
        scatter<<<(E + 255) / 256, 256>>>(a_row[r], a_col[r], a_val[r], E,
                                          wpr, colv + eoff[r], valv + eoff[r]);
    };
    auto spmm = [&](int rel, float* dst, int ldo, int beta) {
        int n = nrows_rel[rel];
        spmm_csr<<<(n * 32 + 255) / 256, 256>>>(rp + rel * RPN, colv + eoff[rel],
                                                valv + eoff[rel], tmp, dst, n, ldo, beta);
    };
    auto round_to = [&](const float* s, float* d, size_t nelem) {
        size_t n4 = nelem / 4;
        tf32_round4<<<(unsigned)((n4 + 255) / 256), 256>>>(s, d, n4);
    };

    // Launch order: #4 is the big M=30000/K=1024 gemm (ncu profiles launch 4).
    do_wt(0, 0);                                      // 1
    round_to(feat0, f0t, (size_t)KN0 * KF);           // 2
    round_to(feat1, f1t, (size_t)KN1 * KF);           // 3
    gemm(f0t, 0, 0, KN0, KF);                         // 4  <- profiled
    for (int r = 0; r < 5; r++) build_csr(r);
    spmm(0, e00, KH, 0);
    do_wt(0, 1);
    gemm(f1t, 0, 1, KN1, KF); spmm(1, e00, KH, 1);
    relu_dual_t<<<(KN0 * 128 + 255) / 256, 256>>>(e00, out, e00t, KN0);

    do_wt(0, 2); do_wt(0, 3); do_wt(0, 4);
    gemm(f0t, 0, 2, KN0, KF); spmm(2, e01, KH, 0);
    gemm(f1t, 0, 3, KN1, KF); spmm(3, e01, KH, 1);
    gemm(f1t, 0, 4, KN1, KF); spmm(4, e01, KH, 1);
    relu_dual_t<<<(KN1 * 128 + 255) / 256, 256>>>(e01, out + (size_t)KN0 * LDO, e01t, KN1);

    for (int r = 0; r < 5; r++) { do_wt(1, r); do_wt(2, r); }

    // ---------------- Layer 2 (K = H = 512) ----------------
    gemm(e00t, 1, 0, KN0, KH); spmm(0, e20, KH, 0);
    gemm(e01t, 1, 1, KN1, KH); spmm(1, e20, KH, 1);
    relu_t<<<((size_t)KN0 * KH / 4 + 255) / 256, 256>>>(e20, e20t, (size_t)KN0 * KH / 4);

    gemm(e00t, 1, 2, KN0, KH); spmm(2, e21, KH, 0);
    gemm(e01t, 1, 3, KN1, KH); spmm(3, e21, KH, 1);
    gemm(e01t, 1, 4, KN1, KH); spmm(4, e21, KH, 1);
    relu_t<<<((size_t)KN1 * KH / 4 + 255) / 256, 256>>>(e21, e21t, (size_t)KN1 * KH / 4);

    // ---------------- Layer 3 (into d_out cols 1024:1536) ----------------
    float* out3_t0 = out + 1024;
    float* out3_t1 = out + (size_t)KN0 * LDO + 1024;
    gemm(e20t, 2, 0, KN0, KH); spmm(0, out3_t0, LDO, 0);
    gemm(e21t, 2, 1, KN1, KH); spmm(1, out3_t0, LDO, 1);
    gemm(e20t, 2, 2, KN0, KH); spmm(2, out3_t1, LDO, 0);
    gemm(e21t, 2, 3, KN1, KH); spmm(3, out3_t1, LDO, 1);
    gemm(e21t, 2, 4, KN1, KH); spmm(4, out3_t1, LDO, 1);
}

// round 11
// speedup vs baseline: 1.7586x; 1.0219x over previous
#include <cuda_runtime.h>
#include <cuda_bf16.h>
#include <cstdint>
#include <cstddef>

// ============================================================================
// DecagonModel — R11 (R10 resubmit; even-round container flake, content-neutral)
// Fused-N TF32 GEMMs (hoisted addressing) + CSR SpMM.
// Per layer: X0@[Wd0|Wd1] -> tmpA[30000,1024]; X1@[W01|W11a|W11b] -> tmpB[6000,1536].
// ============================================================================

#define KN0 30000
#define KN1 6000
#define KF  1024
#define KH  512
#define LDO 1536
#define ECAP 2100000
#define RPN  30001

// ---------------- device-global scratch -------------------------------------
__device__ float g_tmpA[KN0 * 1024];
__device__ float g_tmpB[KN1 * 1536];
__device__ float g_e00[KN0 * KH];
__device__ float g_e01[KN1 * KH];
__device__ float g_e20[KN0 * KH];
__device__ float g_e21[KN1 * KH];

__device__ float g_f0t[KN0 * KF];
__device__ float g_f1t[KN1 * KF];
__device__ float g_e00t[KN0 * KH];
__device__ float g_e01t[KN1 * KH];
__device__ float g_e20t[KN0 * KH];
__device__ float g_e21t[KN1 * KH];

#define WT_TOTAL 5242880
__device__ float g_wt[WT_TOTAL];

// CSR storage
__device__ int   g_rp[5 * RPN];
__device__ int   g_wp[5 * RPN];
__device__ int   g_colv[ECAP];
__device__ float g_valv[ECAP];

// ---------------- helpers ---------------------------------------------------
__device__ __forceinline__ uint32_t smem_u32(const void* p) {
    uint32_t a;
    asm("{ .reg .u64 t; cvta.to.shared.u64 t, %1; cvt.u32.u64 %0, t; }"
        : "=r"(a) : "l"(p));
    return a;
}
__device__ __forceinline__ void cpa16(uint32_t dst, const void* src, bool v) {
    asm volatile("cp.async.cg.shared.global [%0], [%1], 16, %2;"
                 :: "r"(dst), "l"(src), "r"(v ? 16 : 0) : "memory");
}
__device__ __forceinline__ void ldsm4(uint32_t& r0, uint32_t& r1, uint32_t& r2,
                                      uint32_t& r3, uint32_t addr) {
    asm volatile("ldmatrix.sync.aligned.m8n8.x4.shared.b16 {%0,%1,%2,%3}, [%4];"
                 : "=r"(r0), "=r"(r1), "=r"(r2), "=r"(r3) : "r"(addr));
}
__device__ __forceinline__ void mma_tf32(float& c0, float& c1, float& c2, float& c3,
                                         uint32_t a0, uint32_t a1, uint32_t a2, uint32_t a3,
                                         uint32_t b0, uint32_t b1) {
    asm volatile(
        "mma.sync.aligned.m16n8k8.row.col.f32.tf32.tf32.f32 "
        "{%0,%1,%2,%3}, {%4,%5,%6,%7}, {%8,%9}, {%0,%1,%2,%3};"
        : "+f"(c0), "+f"(c1), "+f"(c2), "+f"(c3)
        : "r"(a0), "r"(a1), "r"(a2), "r"(a3), "r"(b0), "r"(b1));
}
__device__ __forceinline__ float tf32r(float x) {
    uint32_t r;
    asm("cvt.rna.tf32.f32 %0, %1;" : "=r"(r) : "f"(x));
    return __uint_as_float(r);
}

// ----------------------------------------------------------------------------
// TF32 GEMM: C[M,N] = A[M,K] @ B^T (B stored [N,K]).  grid (N/128, ceil(M/128)).
// CTA 128x128, BK=32, 3-stage cp.async, 256 threads, warp tile 64x32.
// All load/ldsm addressing hoisted out of the main loop.
// ----------------------------------------------------------------------------
#define STG_BYTES 32768u
#define GEMM_SMEM (3 * STG_BYTES)

__global__ __launch_bounds__(256) void gemm_tf32(
    const float* __restrict__ A, const float* __restrict__ B,
    float* __restrict__ C, int M, int N, int K)
{
    extern __shared__ char dyn_smem[];
    const uint32_t sbase = smem_u32(dyn_smem);

    const int tid  = threadIdx.x;
    const int wid  = tid >> 5;
    const int lane = tid & 31;
    const int bm   = blockIdx.y * 128;
    const int bn   = blockIdx.x * 128;
    const int wm   = (wid & 1) * 64;
    const int wn   = (wid >> 1) * 32;

    const int NC = K >> 5;

    // ---- hoisted loader state: 4 A rows + 4 B rows per thread, 16B each ----
    const int r0 = tid >> 3, cs = tid & 7;
    const uint32_t d0 = (uint32_t)(r0 * 128 + ((cs * 16) ^ ((r0 & 7) << 4)));
    const float* pA[4]; const float* pB[4]; bool vA[4];
#pragma unroll
    for (int it = 0; it < 4; it++) {
        int r  = r0 + 32 * it;
        int gr = bm + r;
        vA[it] = gr < M;
        pA[it] = A + (size_t)(vA[it] ? gr : 0) * K + cs * 4;
        pB[it] = B + (size_t)(bn + r) * K + cs * 4;
    }

    // ---- hoisted ldsm offsets (stage-relative); addr = stage + (off ^ kb) ----
    const int mi  = lane >> 3;
    const int r8  = lane & 7;
    const int aro = (mi & 1) * 8 + r8;
    const int akb = (mi >> 1) * 16;
    uint32_t offA[4], offB[2];
#pragma unroll
    for (int i = 0; i < 4; i++) {
        int r = wm + i * 16 + aro;
        offA[i] = (uint32_t)(r * 128 + (akb ^ ((r & 7) << 4)));
    }
#pragma unroll
    for (int j2 = 0; j2 < 2; j2++) {
        int r = wn + j2 * 16 + aro;
        offB[j2] = (uint32_t)(16384 + r * 128 + (akb ^ ((r & 7) << 4)));
    }

    float acc[4][4][4];
#pragma unroll
    for (int i = 0; i < 4; i++)
#pragma unroll
        for (int j = 0; j < 4; j++)
#pragma unroll
            for (int q = 0; q < 4; q++) acc[i][j][q] = 0.f;

    auto load_chunk = [&](uint32_t stW) {
        const uint32_t dA = sbase + stW + d0;
#pragma unroll
        for (int it = 0; it < 4; it++) {
            cpa16(dA + 4096u * it,          pA[it], vA[it]);
            cpa16(dA + 16384u + 4096u * it, pB[it], true);
            pA[it] += 32; pB[it] += 32;
        }
        asm volatile("cp.async.commit_group;" ::: "memory");
    };

    uint32_t stW = 0, stR = 0;
    load_chunk(stW); stW = STG_BYTES;
    load_chunk(stW); stW = 2 * STG_BYTES;

    for (int c = 0; c < NC; c++) {
        asm volatile("cp.async.wait_group 1;" ::: "memory");
        __syncthreads();
        if (c + 2 < NC) {
            load_chunk(stW);
            stW += STG_BYTES; if (stW == 3 * STG_BYTES) stW = 0;
        }

        const uint32_t st = sbase + stR;
        stR += STG_BYTES; if (stR == 3 * STG_BYTES) stR = 0;

#pragma unroll
        for (int s = 0; s < 4; s++) {
            const uint32_t kb = s * 32;
            uint32_t a[4][4], bf[4][2];
            #pragma unroll
            for (int i = 0; i < 4; i++)
                ldsm4(a[i][0], a[i][1], a[i][2], a[i][3], st + (offA[i] ^ kb));
            #pragma unroll
            for (int j2 = 0; j2 < 2; j2++) {
                uint32_t q0, q1, q2, q3;
                ldsm4(q0, q1, q2, q3, st + (offB[j2] ^ kb));
                bf[j2 * 2][0]     = q0; bf[j2 * 2][1]     = q2;
                bf[j2 * 2 + 1][0] = q1; bf[j2 * 2 + 1][1] = q3;
            }
            #pragma unroll
            for (int i = 0; i < 4; i++)
                #pragma unroll
                for (int j = 0; j < 4; j++)
                    mma_tf32(acc[i][j][0], acc[i][j][1], acc[i][j][2], acc[i][j][3],
                             a[i][0], a[i][1], a[i][2], a[i][3],
                             bf[j][0], bf[j][1]);
        }
    }

    const int lm = lane >> 2, ln = (lane & 3) * 2;
#pragma unroll
    for (int i = 0; i < 4; i++) {
#pragma unroll
        for (int j = 0; j < 4; j++) {
            int m0 = bm + wm + i * 16 + lm;
            int n0 = bn + wn + j * 8 + ln;
            if (m0 < M)
                *(float2*)(C + (size_t)m0 * N + n0) =
                    make_float2(acc[i][j][0], acc[i][j][1]);
            if (m0 + 8 < M)
                *(float2*)(C + (size_t)(m0 + 8) * N + n0) =
                    make_float2(acc[i][j][2], acc[i][j][3]);
        }
    }
}

// ----------------------------------------------------------------------------
// CSR build kernels
// ----------------------------------------------------------------------------
__global__ void seti(int* __restrict__ p, int n, int v)
{
    int i = blockIdx.x * blockDim.x + threadIdx.x;
    if (i < n) p[i] = v;
}
__global__ void hist(const int* __restrict__ row, int E, int* __restrict__ cnt)
{
    int i = blockIdx.x * blockDim.x + threadIdx.x;
    if (i < E) atomicAdd(&cnt[row[i]], 1);
}
__global__ void exscan(const int* __restrict__ cnt, int* __restrict__ rp, int n)
{
    __shared__ int part[1024];
    const int t = threadIdx.x;
    const int chunk = (n + 1 + 1023) / 1024;
    const int base = t * chunk;
    int s = 0;
    for (int i = 0; i < chunk; i++) {
        int idx = base + i;
        if (idx < n) s += cnt[idx];
    }
    part[t] = s;
    __syncthreads();
    for (int off = 1; off < 1024; off <<= 1) {
        int v = (t >= off) ? part[t - off] : 0;
        __syncthreads();
        part[t] += v;
        __syncthreads();
    }
    int run = part[t] - s;
    for (int i = 0; i < chunk; i++) {
        int idx = base + i;
        if (idx <= n) {
            rp[idx] = run;
            if (idx < n) run += cnt[idx];
        }
    }
}
__global__ void copyi(const int* __restrict__ s, int* __restrict__ d, int n)
{
    int i = blockIdx.x * blockDim.x + threadIdx.x;
    if (i < n) d[i] = s[i];
}
__global__ void scatter(const int* __restrict__ row, const int* __restrict__ col,
                        const float* __restrict__ val, int E,
                        int* __restrict__ wp, int* __restrict__ colv,
                        float* __restrict__ valv)
{
    int i = blockIdx.x * blockDim.x + threadIdx.x;
    if (i >= E) return;
    int p = atomicAdd(&wp[row[i]], 1);
    colv[p] = col[i];
    valv[p] = val[i];
}

// ----------------------------------------------------------------------------
// CSR SpMM: warp per output row; x has row stride ldx (pre-offset by column).
// ----------------------------------------------------------------------------
__global__ __launch_bounds__(256) void spmm_csr(
    const int* __restrict__ rp, const int* __restrict__ colv,
    const float* __restrict__ valv, const float* __restrict__ x, int ldx,
    float* __restrict__ out, int nrows, int ldo, int beta)
{
    int row  = (blockIdx.x * blockDim.x + threadIdx.x) >> 5;
    int lane = threadIdx.x & 31;
    if (row >= nrows) return;
    int s = rp[row], e = rp[row + 1];

    float4 a0 = make_float4(0.f, 0.f, 0.f, 0.f), a1 = a0, a2 = a0, a3 = a0;

#pragma unroll 2
    for (int i = s; i < e; i++) {
        int   c = __ldg(&colv[i]);
        float v = __ldg(&valv[i]);
        const float4* xr = reinterpret_cast<const float4*>(x + (size_t)c * ldx);
        float4 t;
        t = xr[lane];
        a0.x = fmaf(v, t.x, a0.x); a0.y = fmaf(v, t.y, a0.y);
        a0.z = fmaf(v, t.z, a0.z); a0.w = fmaf(v, t.w, a0.w);
        t = xr[lane + 32];
        a1.x = fmaf(v, t.x, a1.x); a1.y = fmaf(v, t.y, a1.y);
        a1.z = fmaf(v, t.z, a1.z); a1.w = fmaf(v, t.w, a1.w);
        t = xr[lane + 64];
        a2.x = fmaf(v, t.x, a2.x); a2.y = fmaf(v, t.y, a2.y);
        a2.z = fmaf(v, t.z, a2.z); a2.w = fmaf(v, t.w, a2.w);
        t = xr[lane + 96];
        a3.x = fmaf(v, t.x, a3.x); a3.y = fmaf(v, t.y, a3.y);
        a3.z = fmaf(v, t.z, a3.z); a3.w = fmaf(v, t.w, a3.w);
    }

    float4* o = reinterpret_cast<float4*>(out + (size_t)row * ldo);
    if (beta) {
        float4 t;
        t = o[lane];      a0.x += t.x; a0.y += t.y; a0.z += t.z; a0.w += t.w;
        t = o[lane + 32]; a1.x += t.x; a1.y += t.y; a1.z += t.z; a1.w += t.w;
        t = o[lane + 64]; a2.x += t.x; a2.y += t.y; a2.z += t.z; a2.w += t.w;
        t = o[lane + 96]; a3.x += t.x; a3.y += t.y; a3.z += t.z; a3.w += t.w;
    }
    o[lane]      = a0;
    o[lane + 32] = a1;
    o[lane + 64] = a2;
    o[lane + 96] = a3;
}

// ----------------------------------------------------------------------------
// Converters / epilogues
// ----------------------------------------------------------------------------
__global__ void tf32_round4(const float* __restrict__ x, float* __restrict__ y, size_t n4)
{
    size_t i = blockIdx.x * (size_t)blockDim.x + threadIdx.x;
    if (i >= n4) return;
    float4 t = reinterpret_cast<const float4*>(x)[i];
    t.x = tf32r(t.x); t.y = tf32r(t.y); t.z = tf32r(t.z); t.w = tf32r(t.w);
    reinterpret_cast<float4*>(y)[i] = t;
}

// W [K,512] f32 -> T rows [512, K] tf32-rounded (T pre-offset to row group)
__global__ void wt_t(const float* __restrict__ W, float* __restrict__ T, int K)
{
    __shared__ float t[32][33];
    int kb = blockIdx.x * 32, nb = blockIdx.y * 32;
    int x = threadIdx.x, y = threadIdx.y;
#pragma unroll
    for (int i = 0; i < 32; i += 8)
        t[y + i][x] = W[(size_t)(kb + y + i) * KH + nb + x];
    __syncthreads();
#pragma unroll
    for (int i = 0; i < 32; i += 8)
        T[(size_t)(nb + y + i) * K + kb + x] = tf32r(t[x][y + i]);
}

__global__ void relu_dual_t(const float* __restrict__ e, float* __restrict__ outbase,
                            float* __restrict__ et, int n)
{
    int idx = blockIdx.x * blockDim.x + threadIdx.x;
    if (idx >= n * 128) return;
    float4 t = reinterpret_cast<const float4*>(e)[idx];
    t.x = fmaxf(t.x, 0.f); t.y = fmaxf(t.y, 0.f);
    t.z = fmaxf(t.z, 0.f); t.w = fmaxf(t.w, 0.f);
    int r = idx >> 7, c = idx & 127;
    float4* o = reinterpret_cast<float4*>(outbase + (size_t)r * LDO);
    o[c]       = t;
    o[c + 128] = t;
    t.x = tf32r(t.x); t.y = tf32r(t.y); t.z = tf32r(t.z); t.w = tf32r(t.w);
    reinterpret_cast<float4*>(et)[idx] = t;
}

__global__ void relu_t(const float* __restrict__ e, float* __restrict__ et, size_t n4)
{
    size_t i = blockIdx.x * (size_t)blockDim.x + threadIdx.x;
    if (i >= n4) return;
    float4 t = reinterpret_cast<const float4*>(e)[i];
    t.x = tf32r(fmaxf(t.x, 0.f)); t.y = tf32r(fmaxf(t.y, 0.f));
    t.z = tf32r(fmaxf(t.z, 0.f)); t.w = tf32r(fmaxf(t.w, 0.f));
    reinterpret_cast<float4*>(et)[i] = t;
}

// ----------------------------------------------------------------------------
// Host orchestration
// ----------------------------------------------------------------------------
extern "C" void kernel_launch(void* const* d_in, const int* in_sizes, int n_in,
                              void* d_out, int out_size)
{
    const float* feat0 = (const float*)d_in[0];
    const float* feat1 = (const float*)d_in[1];

    const int*   a_row[5]; const int* a_col[5]; const float* a_val[5]; int Ecnt[5];
    for (int i = 0; i < 5; i++) {
        a_row[i] = (const int*)d_in[2 + 3 * i];
        a_col[i] = (const int*)d_in[3 + 3 * i];
        a_val[i] = (const float*)d_in[4 + 3 * i];
        Ecnt[i]  = in_sizes[2 + 3 * i];
    }
    const int nrows_rel[5] = {KN0, KN0, KN1, KN1, KN1};
    const float* W[3][5];
    for (int r = 0; r < 5; r++)
        for (int l = 0; l < 3; l++)
            W[l][r] = (const float*)d_in[17 + 3 * r + l];

    float *tmpA, *tmpB, *e00, *e01, *e20, *e21;
    float *f0t, *f1t, *e00t, *e01t, *e20t, *e21t, *wt;
    int *rp, *wp, *colv; float *valv;
    {
        void* p;
        cudaGetSymbolAddress(&p, g_tmpA); tmpA = (float*)p;
        cudaGetSymbolAddress(&p, g_tmpB); tmpB = (float*)p;
        cudaGetSymbolAddress(&p, g_e00);  e00  = (float*)p;
        cudaGetSymbolAddress(&p, g_e01);  e01  = (float*)p;
        cudaGetSymbolAddress(&p, g_e20);  e20  = (float*)p;
        cudaGetSymbolAddress(&p, g_e21);  e21  = (float*)p;
        cudaGetSymbolAddress(&p, g_f0t);  f0t  = (float*)p;
        cudaGetSymbolAddress(&p, g_f1t);  f1t  = (float*)p;
        cudaGetSymbolAddress(&p, g_e00t); e00t = (float*)p;
        cudaGetSymbolAddress(&p, g_e01t); e01t = (float*)p;
        cudaGetSymbolAddress(&p, g_e20t); e20t = (float*)p;
        cudaGetSymbolAddress(&p, g_e21t); e21t = (float*)p;
        cudaGetSymbolAddress(&p, g_wt);   wt   = (float*)p;
        cudaGetSymbolAddress(&p, g_rp);   rp   = (int*)p;
        cudaGetSymbolAddress(&p, g_wp);   wp   = (int*)p;
        cudaGetSymbolAddress(&p, g_colv); colv = (int*)p;
        cudaGetSymbolAddress(&p, g_valv); valv = (float*)p;
    }
    float* out = (float*)d_out;

    // fused weight blocks: WA_l [1024,K], WB_l [1536,K]
    const size_t WA_off[3] = {0, 2621440, 3932160};
    const size_t WB_off[3] = {1048576, 3145728, 4456448};
    const int    Kl[3]     = {KF, KH, KH};

    size_t eoff[5]; size_t acc_e = 0;
    for (int r = 0; r < 5; r++) { eoff[r] = acc_e; acc_e += (size_t)Ecnt[r]; }

    cudaFuncSetAttribute(gemm_tf32, cudaFuncAttributeMaxDynamicSharedMemorySize, GEMM_SMEM);

    auto do_wt = [&](int l, int rel, float* dst_base, int rowoff) {
        int K = Kl[l];
        wt_t<<<dim3(K / 32, KH / 32), dim3(32, 8)>>>(W[l][rel],
                                                     dst_base + (size_t)rowoff * K, K);
    };
    auto gemm = [&](const float* A, const float* B, float* C, int M, int N, int K) {
        dim3 grid(N / 128, (M + 127) / 128);
        gemm_tf32<<<grid, 256, GEMM_SMEM>>>(A, B, C, M, N, K);
    };
    auto build_csr = [&](int r) {
        int n = nrows_rel[r], E = Ecnt[r];
        int* rpr = rp + r * RPN;
        int* wpr = wp + r * RPN;
        seti<<<(n + 255) / 256, 256>>>(wpr, n, 0);
        hist<<<(E + 255) / 256, 256>>>(a_row[r], E, wpr);
        exscan<<<1, 1024>>>(wpr, rpr, n);
        copyi<<<(n + 255) / 256, 256>>>(rpr, wpr, n);
        scatter<<<(E + 255) / 256, 256>>>(a_row[r], a_col[r], a_val[r], E,
                                          wpr, colv + eoff[r], valv + eoff[r]);
    };
    // rel -> (x base, ldx, col offset)
    auto spmm = [&](int rel, float* dst, int ldo, int beta) {
        int n = nrows_rel[rel];
        const float* x; int ldx;
        switch (rel) {
            case 0: x = tmpA;        ldx = 1024; break;
            case 1: x = tmpB;        ldx = 1536; break;
            case 2: x = tmpA + 512;  ldx = 1024; break;
            case 3: x = tmpB + 512;  ldx = 1536; break;
            default: x = tmpB + 1024; ldx = 1536; break;
        }
        spmm_csr<<<(n * 32 + 255) / 256, 256>>>(rp + rel * RPN, colv + eoff[rel],
                                                valv + eoff[rel], x, ldx, dst, n, ldo, beta);
    };
    auto round_to = [&](const float* s, float* d, size_t nelem) {
        size_t n4 = nelem / 4;
        tf32_round4<<<(unsigned)((n4 + 255) / 256), 256>>>(s, d, n4);
    };

    float* wA1 = wt + WA_off[0];
    float* wB1 = wt + WB_off[0];

    // Launch order: #4 is the big fused M=30000/N=1024/K=1024 gemm (profiled).
    do_wt(0, 0, wA1, 0);                              // 1
    do_wt(0, 2, wA1, 512);                            // 2
    round_to(feat0, f0t, (size_t)KN0 * KF);           // 3
    gemm(f0t, wA1, tmpA, KN0, 1024, KF);              // 4  <- profiled
    round_to(feat1, f1t, (size_t)KN1 * KF);           // 5
    do_wt(0, 1, wB1, 0);
    do_wt(0, 3, wB1, 512);
    do_wt(0, 4, wB1, 1024);
    gemm(f1t, wB1, tmpB, KN1, 1536, KF);
    for (int r = 0; r < 5; r++) build_csr(r);

    // ---------------- Layer 1 epilogue ----------------
    spmm(0, e00, KH, 0); spmm(1, e00, KH, 1);
    relu_dual_t<<<(KN0 * 128 + 255) / 256, 256>>>(e00, out, e00t, KN0);
    spmm(2, e01, KH, 0); spmm(3, e01, KH, 1); spmm(4, e01, KH, 1);
    relu_dual_t<<<(KN1 * 128 + 255) / 256, 256>>>(e01, out + (size_t)KN0 * LDO, e01t, KN1);

    // weights for layers 2,3
    for (int l = 1; l < 3; l++) {
        do_wt(l, 0, wt + WA_off[l], 0);
        do_wt(l, 2, wt + WA_off[l], 512);
        do_wt(l, 1, wt + WB_off[l], 0);
        do_wt(l, 3, wt + WB_off[l], 512);
        do_wt(l, 4, wt + WB_off[l], 1024);
    }

    // ---------------- Layer 2 ----------------
    gemm(e00t, wt + WA_off[1], tmpA, KN0, 1024, KH);
    gemm(e01t, wt + WB_off[1], tmpB, KN1, 1536, KH);
    spmm(0, e20, KH, 0); spmm(1, e20, KH, 1);
    relu_t<<<((size_t)KN0 * KH / 4 + 255) / 256, 256>>>(e20, e20t, (size_t)KN0 * KH / 4);
    spmm(2, e21, KH, 0); spmm(3, e21, KH, 1); spmm(4, e21, KH, 1);
    relu_t<<<((size_t)KN1 * KH / 4 + 255) / 256, 256>>>(e21, e21t, (size_t)KN1 * KH / 4);

    // ---------------- Layer 3 (into d_out cols 1024:1536) ----------------
    gemm(e20t, wt + WA_off[2], tmpA, KN0, 1024, KH);
    gemm(e21t, wt + WB_off[2], tmpB, KN1, 1536, KH);
    float* out3_t0 = out + 1024;
    float* out3_t1 = out + (size_t)KN0 * LDO + 1024;
    spmm(0, out3_t0, LDO, 0); spmm(1, out3_t0, LDO, 1);
    spmm(2, out3_t1, LDO, 0); spmm(3, out3_t1, LDO, 1); spmm(4, out3_t1, LDO, 1);
}

// round 12
// speedup vs baseline: 1.8755x; 1.0665x over previous
#include <cuda_runtime.h>
#include <cuda_bf16.h>
#include <cstdint>
#include <cstddef>

// ============================================================================
// DecagonModel — R12: R11 + register-level fragment double-buffering in the
// TF32 GEMM mainloop (hide LDSM latency under MMA issue).
// ============================================================================

#define KN0 30000
#define KN1 6000
#define KF  1024
#define KH  512
#define LDO 1536
#define ECAP 2100000
#define RPN  30001

// ---------------- device-global scratch -------------------------------------
__device__ float g_tmpA[KN0 * 1024];
__device__ float g_tmpB[KN1 * 1536];
__device__ float g_e00[KN0 * KH];
__device__ float g_e01[KN1 * KH];
__device__ float g_e20[KN0 * KH];
__device__ float g_e21[KN1 * KH];

__device__ float g_f0t[KN0 * KF];
__device__ float g_f1t[KN1 * KF];
__device__ float g_e00t[KN0 * KH];
__device__ float g_e01t[KN1 * KH];
__device__ float g_e20t[KN0 * KH];
__device__ float g_e21t[KN1 * KH];

#define WT_TOTAL 5242880
__device__ float g_wt[WT_TOTAL];

__device__ int   g_rp[5 * RPN];
__device__ int   g_wp[5 * RPN];
__device__ int   g_colv[ECAP];
__device__ float g_valv[ECAP];

// ---------------- helpers ---------------------------------------------------
__device__ __forceinline__ uint32_t smem_u32(const void* p) {
    uint32_t a;
    asm("{ .reg .u64 t; cvta.to.shared.u64 t, %1; cvt.u32.u64 %0, t; }"
        : "=r"(a) : "l"(p));
    return a;
}
__device__ __forceinline__ void cpa16(uint32_t dst, const void* src, bool v) {
    asm volatile("cp.async.cg.shared.global [%0], [%1], 16, %2;"
                 :: "r"(dst), "l"(src), "r"(v ? 16 : 0) : "memory");
}
__device__ __forceinline__ void ldsm4(uint32_t& r0, uint32_t& r1, uint32_t& r2,
                                      uint32_t& r3, uint32_t addr) {
    asm volatile("ldmatrix.sync.aligned.m8n8.x4.shared.b16 {%0,%1,%2,%3}, [%4];"
                 : "=r"(r0), "=r"(r1), "=r"(r2), "=r"(r3) : "r"(addr));
}
__device__ __forceinline__ void mma_tf32(float& c0, float& c1, float& c2, float& c3,
                                         uint32_t a0, uint32_t a1, uint32_t a2, uint32_t a3,
                                         uint32_t b0, uint32_t b1) {
    asm volatile(
        "mma.sync.aligned.m16n8k8.row.col.f32.tf32.tf32.f32 "
        "{%0,%1,%2,%3}, {%4,%5,%6,%7}, {%8,%9}, {%0,%1,%2,%3};"
        : "+f"(c0), "+f"(c1), "+f"(c2), "+f"(c3)
        : "r"(a0), "r"(a1), "r"(a2), "r"(a3), "r"(b0), "r"(b1));
}
__device__ __forceinline__ float tf32r(float x) {
    uint32_t r;
    asm("cvt.rna.tf32.f32 %0, %1;" : "=r"(r) : "f"(x));
    return __uint_as_float(r);
}

// ----------------------------------------------------------------------------
// TF32 GEMM: C[M,N] = A[M,K] @ B^T (B stored [N,K]).  grid (N/128, ceil(M/128)).
// CTA 128x128, BK=32, 3-stage cp.async, 256 threads, warp tile 64x32.
// Fragment double-buffering: k8 step s+1 LDSMs issue before step s MMAs.
// ----------------------------------------------------------------------------
#define STG_BYTES 32768u
#define GEMM_SMEM (3 * STG_BYTES)

__global__ __launch_bounds__(256) void gemm_tf32(
    const float* __restrict__ A, const float* __restrict__ B,
    float* __restrict__ C, int M, int N, int K)
{
    extern __shared__ char dyn_smem[];
    const uint32_t sbase = smem_u32(dyn_smem);

    const int tid  = threadIdx.x;
    const int wid  = tid >> 5;
    const int lane = tid & 31;
    const int bm   = blockIdx.y * 128;
    const int bn   = blockIdx.x * 128;
    const int wm   = (wid & 1) * 64;
    const int wn   = (wid >> 1) * 32;

    const int NC = K >> 5;

    // hoisted loader state
    const int r0 = tid >> 3, cs = tid & 7;
    const uint32_t d0 = (uint32_t)(r0 * 128 + ((cs * 16) ^ ((r0 & 7) << 4)));
    const float* pA[4]; const float* pB[4]; bool vA[4];
#pragma unroll
    for (int it = 0; it < 4; it++) {
        int r  = r0 + 32 * it;
        int gr = bm + r;
        vA[it] = gr < M;
        pA[it] = A + (size_t)(vA[it] ? gr : 0) * K + cs * 4;
        pB[it] = B + (size_t)(bn + r) * K + cs * 4;
    }

    // hoisted ldsm offsets; addr = stage + (off ^ kb), kb = 32*s
    const int mi  = lane >> 3;
    const int r8  = lane & 7;
    const int aro = (mi & 1) * 8 + r8;
    const int akb = (mi >> 1) * 16;
    uint32_t offA[4], offB[2];
#pragma unroll
    for (int i = 0; i < 4; i++) {
        int r = wm + i * 16 + aro;
        offA[i] = (uint32_t)(r * 128 + (akb ^ ((r & 7) << 4)));
    }
#pragma unroll
    for (int j2 = 0; j2 < 2; j2++) {
        int r = wn + j2 * 16 + aro;
        offB[j2] = (uint32_t)(16384 + r * 128 + (akb ^ ((r & 7) << 4)));
    }

    float acc[4][4][4];
#pragma unroll
    for (int i = 0; i < 4; i++)
#pragma unroll
        for (int j = 0; j < 4; j++)
#pragma unroll
            for (int q = 0; q < 4; q++) acc[i][j][q] = 0.f;

    auto load_chunk = [&](uint32_t stW) {
        const uint32_t dA = sbase + stW + d0;
#pragma unroll
        for (int it = 0; it < 4; it++) {
            cpa16(dA + 4096u * it,          pA[it], vA[it]);
            cpa16(dA + 16384u + 4096u * it, pB[it], true);
            pA[it] += 32; pB[it] += 32;
        }
        asm volatile("cp.async.commit_group;" ::: "memory");
    };

    uint32_t stW = 0, stR = 0;
    load_chunk(stW); stW = STG_BYTES;
    load_chunk(stW); stW = 2 * STG_BYTES;

    // double-buffered fragments
    uint32_t fa[2][4][4], fb[2][4][2];

    auto load_frags = [&](uint32_t st, uint32_t kb, int buf) {
#pragma unroll
        for (int i = 0; i < 4; i++)
            ldsm4(fa[buf][i][0], fa[buf][i][1], fa[buf][i][2], fa[buf][i][3],
                  st + (offA[i] ^ kb));
#pragma unroll
        for (int j2 = 0; j2 < 2; j2++) {
            uint32_t q0, q1, q2, q3;
            ldsm4(q0, q1, q2, q3, st + (offB[j2] ^ kb));
            fb[buf][j2 * 2][0]     = q0; fb[buf][j2 * 2][1]     = q2;
            fb[buf][j2 * 2 + 1][0] = q1; fb[buf][j2 * 2 + 1][1] = q3;
        }
    };
    auto do_mmas = [&](int buf) {
#pragma unroll
        for (int i = 0; i < 4; i++)
#pragma unroll
            for (int j = 0; j < 4; j++)
                mma_tf32(acc[i][j][0], acc[i][j][1], acc[i][j][2], acc[i][j][3],
                         fa[buf][i][0], fa[buf][i][1], fa[buf][i][2], fa[buf][i][3],
                         fb[buf][j][0], fb[buf][j][1]);
    };

    for (int c = 0; c < NC; c++) {
        asm volatile("cp.async.wait_group 1;" ::: "memory");
        __syncthreads();
        if (c + 2 < NC) {
            load_chunk(stW);
            stW += STG_BYTES; if (stW == 3 * STG_BYTES) stW = 0;
        }

        const uint32_t st = sbase + stR;
        stR += STG_BYTES; if (stR == 3 * STG_BYTES) stR = 0;

        load_frags(st, 0, 0);              // prime s=0
#pragma unroll
        for (int s = 0; s < 4; s++) {
            if (s < 3) load_frags(st, (uint32_t)(32 * (s + 1)), (s + 1) & 1);
            do_mmas(s & 1);
        }
    }

    const int lm = lane >> 2, ln = (lane & 3) * 2;
#pragma unroll
    for (int i = 0; i < 4; i++) {
#pragma unroll
        for (int j = 0; j < 4; j++) {
            int m0 = bm + wm + i * 16 + lm;
            int n0 = bn + wn + j * 8 + ln;
            if (m0 < M)
                *(float2*)(C + (size_t)m0 * N + n0) =
                    make_float2(acc[i][j][0], acc[i][j][1]);
            if (m0 + 8 < M)
                *(float2*)(C + (size_t)(m0 + 8) * N + n0) =
                    make_float2(acc[i][j][2], acc[i][j][3]);
        }
    }
}

// ----------------------------------------------------------------------------
// CSR build kernels
// ----------------------------------------------------------------------------
__global__ void seti(int* __restrict__ p, int n, int v)
{
    int i = blockIdx.x * blockDim.x + threadIdx.x;
    if (i < n) p[i] = v;
}
__global__ void hist(const int* __restrict__ row, int E, int* __restrict__ cnt)
{
    int i = blockIdx.x * blockDim.x + threadIdx.x;
    if (i < E) atomicAdd(&cnt[row[i]], 1);
}
__global__ void exscan(const int* __restrict__ cnt, int* __restrict__ rp, int n)
{
    __shared__ int part[1024];
    const int t = threadIdx.x;
    const int chunk = (n + 1 + 1023) / 1024;
    const int base = t * chunk;
    int s = 0;
    for (int i = 0; i < chunk; i++) {
        int idx = base + i;
        if (idx < n) s += cnt[idx];
    }
    part[t] = s;
    __syncthreads();
    for (int off = 1; off < 1024; off <<= 1) {
        int v = (t >= off) ? part[t - off] : 0;
        __syncthreads();
        part[t] += v;
        __syncthreads();
    }
    int run = part[t] - s;
    for (int i = 0; i < chunk; i++) {
        int idx = base + i;
        if (idx <= n) {
            rp[idx] = run;
            if (idx < n) run += cnt[idx];
        }
    }
}
__global__ void copyi(const int* __restrict__ s, int* __restrict__ d, int n)
{
    int i = blockIdx.x * blockDim.x + threadIdx.x;
    if (i < n) d[i] = s[i];
}
__global__ void scatter(const int* __restrict__ row, const int* __restrict__ col,
                        const float* __restrict__ val, int E,
                        int* __restrict__ wp, int* __restrict__ colv,
                        float* __restrict__ valv)
{
    int i = blockIdx.x * blockDim.x + threadIdx.x;
    if (i >= E) return;
    int p = atomicAdd(&wp[row[i]], 1);
    colv[p] = col[i];
    valv[p] = val[i];
}

// ----------------------------------------------------------------------------
// CSR SpMM
// ----------------------------------------------------------------------------
__global__ __launch_bounds__(256) void spmm_csr(
    const int* __restrict__ rp, const int* __restrict__ colv,
    const float* __restrict__ valv, const float* __restrict__ x, int ldx,
    float* __restrict__ out, int nrows, int ldo, int beta)
{
    int row  = (blockIdx.x * blockDim.x + threadIdx.x) >> 5;
    int lane = threadIdx.x & 31;
    if (row >= nrows) return;
    int s = rp[row], e = rp[row + 1];

    float4 a0 = make_float4(0.f, 0.f, 0.f, 0.f), a1 = a0, a2 = a0, a3 = a0;

#pragma unroll 2
    for (int i = s; i < e; i++) {
        int   c = __ldg(&colv[i]);
        float v = __ldg(&valv[i]);
        const float4* xr = reinterpret_cast<const float4*>(x + (size_t)c * ldx);
        float4 t;
        t = xr[lane];
        a0.x = fmaf(v, t.x, a0.x); a0.y = fmaf(v, t.y, a0.y);
        a0.z = fmaf(v, t.z, a0.z); a0.w = fmaf(v, t.w, a0.w);
        t = xr[lane + 32];
        a1.x = fmaf(v, t.x, a1.x); a1.y = fmaf(v, t.y, a1.y);
        a1.z = fmaf(v, t.z, a1.z); a1.w = fmaf(v, t.w, a1.w);
        t = xr[lane + 64];
        a2.x = fmaf(v, t.x, a2.x); a2.y = fmaf(v, t.y, a2.y);
        a2.z = fmaf(v, t.z, a2.z); a2.w = fmaf(v, t.w, a2.w);
        t = xr[lane + 96];
        a3.x = fmaf(v, t.x, a3.x); a3.y = fmaf(v, t.y, a3.y);
        a3.z = fmaf(v, t.z, a3.z); a3.w = fmaf(v, t.w, a3.w);
    }

    float4* o = reinterpret_cast<float4*>(out + (size_t)row * ldo);
    if (beta) {
        float4 t;
        t = o[lane];      a0.x += t.x; a0.y += t.y; a0.z += t.z; a0.w += t.w;
        t = o[lane + 32]; a1.x += t.x; a1.y += t.y; a1.z += t.z; a1.w += t.w;
        t = o[lane + 64]; a2.x += t.x; a2.y += t.y; a2.z += t.z; a2.w += t.w;
        t = o[lane + 96]; a3.x += t.x; a3.y += t.y; a3.z += t.z; a3.w += t.w;
    }
    o[lane]      = a0;
    o[lane + 32] = a1;
    o[lane + 64] = a2;
    o[lane + 96] = a3;
}

// ----------------------------------------------------------------------------
// Converters / epilogues
// ----------------------------------------------------------------------------
__global__ void tf32_round4(const float* __restrict__ x, float* __restrict__ y, size_t n4)
{
    size_t i = blockIdx.x * (size_t)blockDim.x + threadIdx.x;
    if (i >= n4) return;
    float4 t = reinterpret_cast<const float4*>(x)[i];
    t.x = tf32r(t.x); t.y = tf32r(t.y); t.z = tf32r(t.z); t.w = tf32r(t.w);
    reinterpret_cast<float4*>(y)[i] = t;
}

__global__ void wt_t(const float* __restrict__ W, float* __restrict__ T, int K)
{
    __shared__ float t[32][33];
    int kb = blockIdx.x * 32, nb = blockIdx.y * 32;
    int x = threadIdx.x, y = threadIdx.y;
#pragma unroll
    for (int i = 0; i < 32; i += 8)
        t[y + i][x] = W[(size_t)(kb + y + i) * KH + nb + x];
    __syncthreads();
#pragma unroll
    for (int i = 0; i < 32; i += 8)
        T[(size_t)(nb + y + i) * K + kb + x] = tf32r(t[x][y + i]);
}

__global__ void relu_dual_t(const float* __restrict__ e, float* __restrict__ outbase,
                            float* __restrict__ et, int n)
{
    int idx = blockIdx.x * blockDim.x + threadIdx.x;
    if (idx >= n * 128) return;
    float4 t = reinterpret_cast<const float4*>(e)[idx];
    t.x = fmaxf(t.x, 0.f); t.y = fmaxf(t.y, 0.f);
    t.z = fmaxf(t.z, 0.f); t.w = fmaxf(t.w, 0.f);
    int r = idx >> 7, c = idx & 127;
    float4* o = reinterpret_cast<float4*>(outbase + (size_t)r * LDO);
    o[c]       = t;
    o[c + 128] = t;
    t.x = tf32r(t.x); t.y = tf32r(t.y); t.z = tf32r(t.z); t.w = tf32r(t.w);
    reinterpret_cast<float4*>(et)[idx] = t;
}

__global__ void relu_t(const float* __restrict__ e, float* __restrict__ et, size_t n4)
{
    size_t i = blockIdx.x * (size_t)blockDim.x + threadIdx.x;
    if (i >= n4) return;
    float4 t = reinterpret_cast<const float4*>(e)[i];
    t.x = tf32r(fmaxf(t.x, 0.f)); t.y = tf32r(fmaxf(t.y, 0.f));
    t.z = tf32r(fmaxf(t.z, 0.f)); t.w = tf32r(fmaxf(t.w, 0.f));
    reinterpret_cast<float4*>(et)[i] = t;
}

// ----------------------------------------------------------------------------
// Host orchestration
// ----------------------------------------------------------------------------
extern "C" void kernel_launch(void* const* d_in, const int* in_sizes, int n_in,
                              void* d_out, int out_size)
{
    const float* feat0 = (const float*)d_in[0];
    const float* feat1 = (const float*)d_in[1];

    const int*   a_row[5]; const int* a_col[5]; const float* a_val[5]; int Ecnt[5];
    for (int i = 0; i < 5; i++) {
        a_row[i] = (const int*)d_in[2 + 3 * i];
        a_col[i] = (const int*)d_in[3 + 3 * i];
        a_val[i] = (const float*)d_in[4 + 3 * i];
        Ecnt[i]  = in_sizes[2 + 3 * i];
    }
    const int nrows_rel[5] = {KN0, KN0, KN1, KN1, KN1};
    const float* W[3][5];
    for (int r = 0; r < 5; r++)
        for (int l = 0; l < 3; l++)
            W[l][r] = (const float*)d_in[17 + 3 * r + l];

    float *tmpA, *tmpB, *e00, *e01, *e20, *e21;
    float *f0t, *f1t, *e00t, *e01t, *e20t, *e21t, *wt;
    int *rp, *wp, *colv; float *valv;
    {
        void* p;
        cudaGetSymbolAddress(&p, g_tmpA); tmpA = (float*)p;
        cudaGetSymbolAddress(&p, g_tmpB); tmpB = (float*)p;
        cudaGetSymbolAddress(&p, g_e00);  e00  = (float*)p;
        cudaGetSymbolAddress(&p, g_e01);  e01  = (float*)p;
        cudaGetSymbolAddress(&p, g_e20);  e20  = (float*)p;
        cudaGetSymbolAddress(&p, g_e21);  e21  = (float*)p;
        cudaGetSymbolAddress(&p, g_f0t);  f0t  = (float*)p;
        cudaGetSymbolAddress(&p, g_f1t);  f1t  = (float*)p;
        cudaGetSymbolAddress(&p, g_e00t); e00t = (float*)p;
        cudaGetSymbolAddress(&p, g_e01t); e01t = (float*)p;
        cudaGetSymbolAddress(&p, g_e20t); e20t = (float*)p;
        cudaGetSymbolAddress(&p, g_e21t); e21t = (float*)p;
        cudaGetSymbolAddress(&p, g_wt);   wt   = (float*)p;
        cudaGetSymbolAddress(&p, g_rp);   rp   = (int*)p;
        cudaGetSymbolAddress(&p, g_wp);   wp   = (int*)p;
        cudaGetSymbolAddress(&p, g_colv); colv = (int*)p;
        cudaGetSymbolAddress(&p, g_valv); valv = (float*)p;
    }
    float* out = (float*)d_out;

    const size_t WA_off[3] = {0, 2621440, 3932160};
    const size_t WB_off[3] = {1048576, 3145728, 4456448};
    const int    Kl[3]     = {KF, KH, KH};

    size_t eoff[5]; size_t acc_e = 0;
    for (int r = 0; r < 5; r++) { eoff[r] = acc_e; acc_e += (size_t)Ecnt[r]; }

    cudaFuncSetAttribute(gemm_tf32, cudaFuncAttributeMaxDynamicSharedMemorySize, GEMM_SMEM);

    auto do_wt = [&](int l, int rel, float* dst_base, int rowoff) {
        int K = Kl[l];
        wt_t<<<dim3(K / 32, KH / 32), dim3(32, 8)>>>(W[l][rel],
                                                     dst_base + (size_t)rowoff * K, K);
    };
    auto gemm = [&](const float* A, const float* B, float* C, int M, int N, int K) {
        dim3 grid(N / 128, (M + 127) / 128);
        gemm_tf32<<<grid, 256, GEMM_SMEM>>>(A, B, C, M, N, K);
    };
    auto build_csr = [&](int r) {
        int n = nrows_rel[r], E = Ecnt[r];
        int* rpr = rp + r * RPN;
        int* wpr = wp + r * RPN;
        seti<<<(n + 255) / 256, 256>>>(wpr, n, 0);
        hist<<<(E + 255) / 256, 256>>>(a_row[r], E, wpr);
        exscan<<<1, 1024>>>(wpr, rpr, n);
        copyi<<<(n + 255) / 256, 256>>>(rpr, wpr, n);
        scatter<<<(E + 255) / 256, 256>>>(a_row[r], a_col[r], a_val[r], E,
                                          wpr, colv + eoff[r], valv + eoff[r]);
    };
    auto spmm = [&](int rel, float* dst, int ldo, int beta) {
        int n = nrows_rel[rel];
        const float* x; int ldx;
        switch (rel) {
            case 0: x = tmpA;        ldx = 1024; break;
            case 1: x = tmpB;        ldx = 1536; break;
            case 2: x = tmpA + 512;  ldx = 1024; break;
            case 3: x = tmpB + 512;  ldx = 1536; break;
            default: x = tmpB + 1024; ldx = 1536; break;
        }
        spmm_csr<<<(n * 32 + 255) / 256, 256>>>(rp + rel * RPN, colv + eoff[rel],
                                                valv + eoff[rel], x, ldx, dst, n, ldo, beta);
    };
    auto round_to = [&](const float* s, float* d, size_t nelem) {
        size_t n4 = nelem / 4;
        tf32_round4<<<(unsigned)((n4 + 255) / 256), 256>>>(s, d, n4);
    };

    float* wA1 = wt + WA_off[0];
    float* wB1 = wt + WB_off[0];

    // Launch order: #4 is the big fused M=30000/N=1024/K=1024 gemm (profiled).
    do_wt(0, 0, wA1, 0);                              // 1
    do_wt(0, 2, wA1, 512);                            // 2
    round_to(feat0, f0t, (size_t)KN0 * KF);           // 3
    gemm(f0t, wA1, tmpA, KN0, 1024, KF);              // 4  <- profiled
    round_to(feat1, f1t, (size_t)KN1 * KF);           // 5
    do_wt(0, 1, wB1, 0);
    do_wt(0, 3, wB1, 512);
    do_wt(0, 4, wB1, 1024);
    gemm(f1t, wB1, tmpB, KN1, 1536, KF);
    for (int r = 0; r < 5; r++) build_csr(r);

    // ---------------- Layer 1 epilogue ----------------
    spmm(0, e00, KH, 0); spmm(1, e00, KH, 1);
    relu_dual_t<<<(KN0 * 128 + 255) / 256, 256>>>(e00, out, e00t, KN0);
    spmm(2, e01, KH, 0); spmm(3, e01, KH, 1); spmm(4, e01, KH, 1);
    relu_dual_t<<<(KN1 * 128 + 255) / 256, 256>>>(e01, out + (size_t)KN0 * LDO, e01t, KN1);

    for (int l = 1; l < 3; l++) {
        do_wt(l, 0, wt + WA_off[l], 0);
        do_wt(l, 2, wt + WA_off[l], 512);
        do_wt(l, 1, wt + WB_off[l], 0);
        do_wt(l, 3, wt + WB_off[l], 512);
        do_wt(l, 4, wt + WB_off[l], 1024);
    }

    // ---------------- Layer 2 ----------------
    gemm(e00t, wt + WA_off[1], tmpA, KN0, 1024, KH);
    gemm(e01t, wt + WB_off[1], tmpB, KN1, 1536, KH);
    spmm(0, e20, KH, 0); spmm(1, e20, KH, 1);
    relu_t<<<((size_t)KN0 * KH / 4 + 255) / 256, 256>>>(e20, e20t, (size_t)KN0 * KH / 4);
    spmm(2, e21, KH, 0); spmm(3, e21, KH, 1); spmm(4, e21, KH, 1);
    relu_t<<<((size_t)KN1 * KH / 4 + 255) / 256, 256>>>(e21, e21t, (size_t)KN1 * KH / 4);

    // ---------------- Layer 3 (into d_out cols 1024:1536) ----------------
    gemm(e20t, wt + WA_off[2], tmpA, KN0, 1024, KH);
    gemm(e21t, wt + WB_off[2], tmpB, KN1, 1536, KH);
    float* out3_t0 = out + 1024;
    float* out3_t1 = out + (size_t)KN0 * LDO + 1024;
    spmm(0, out3_t0, LDO, 0); spmm(1, out3_t0, LDO, 1);
    spmm(2, out3_t1, LDO, 0); spmm(3, out3_t1, LDO, 1); spmm(4, out3_t1, LDO, 1);
}

// round 13
// speedup vs baseline: 1.9373x; 1.0329x over previous
#include <cuda_runtime.h>
#include <cuda_bf16.h>
#include <cstdint>
#include <cstddef>

// ============================================================================
// DecagonModel — R13: R12 + relu/round/output fused into final SpMM pass.
// ============================================================================

#define KN0 30000
#define KN1 6000
#define KF  1024
#define KH  512
#define LDO 1536
#define ECAP 2100000
#define RPN  30001

// ---------------- device-global scratch -------------------------------------
__device__ float g_tmpA[KN0 * 1024];
__device__ float g_tmpB[KN1 * 1536];

__device__ float g_f0t[KN0 * KF];
__device__ float g_f1t[KN1 * KF];
__device__ float g_e00t[KN0 * KH];   // partial-sum scratch, then relu+tf32 result
__device__ float g_e01t[KN1 * KH];
__device__ float g_e20t[KN0 * KH];
__device__ float g_e21t[KN1 * KH];

#define WT_TOTAL 5242880
__device__ float g_wt[WT_TOTAL];

__device__ int   g_rp[5 * RPN];
__device__ int   g_wp[5 * RPN];
__device__ int   g_colv[ECAP];
__device__ float g_valv[ECAP];

// ---------------- helpers ---------------------------------------------------
__device__ __forceinline__ uint32_t smem_u32(const void* p) {
    uint32_t a;
    asm("{ .reg .u64 t; cvta.to.shared.u64 t, %1; cvt.u32.u64 %0, t; }"
        : "=r"(a) : "l"(p));
    return a;
}
__device__ __forceinline__ void cpa16(uint32_t dst, const void* src, bool v) {
    asm volatile("cp.async.cg.shared.global [%0], [%1], 16, %2;"
                 :: "r"(dst), "l"(src), "r"(v ? 16 : 0) : "memory");
}
__device__ __forceinline__ void ldsm4(uint32_t& r0, uint32_t& r1, uint32_t& r2,
                                      uint32_t& r3, uint32_t addr) {
    asm volatile("ldmatrix.sync.aligned.m8n8.x4.shared.b16 {%0,%1,%2,%3}, [%4];"
                 : "=r"(r0), "=r"(r1), "=r"(r2), "=r"(r3) : "r"(addr));
}
__device__ __forceinline__ void mma_tf32(float& c0, float& c1, float& c2, float& c3,
                                         uint32_t a0, uint32_t a1, uint32_t a2, uint32_t a3,
                                         uint32_t b0, uint32_t b1) {
    asm volatile(
        "mma.sync.aligned.m16n8k8.row.col.f32.tf32.tf32.f32 "
        "{%0,%1,%2,%3}, {%4,%5,%6,%7}, {%8,%9}, {%0,%1,%2,%3};"
        : "+f"(c0), "+f"(c1), "+f"(c2), "+f"(c3)
        : "r"(a0), "r"(a1), "r"(a2), "r"(a3), "r"(b0), "r"(b1));
}
__device__ __forceinline__ float tf32r(float x) {
    uint32_t r;
    asm("cvt.rna.tf32.f32 %0, %1;" : "=r"(r) : "f"(x));
    return __uint_as_float(r);
}

// ----------------------------------------------------------------------------
// TF32 GEMM (R12 mainloop: hoisted addressing + fragment double-buffering)
// ----------------------------------------------------------------------------
#define STG_BYTES 32768u
#define GEMM_SMEM (3 * STG_BYTES)

__global__ __launch_bounds__(256) void gemm_tf32(
    const float* __restrict__ A, const float* __restrict__ B,
    float* __restrict__ C, int M, int N, int K)
{
    extern __shared__ char dyn_smem[];
    const uint32_t sbase = smem_u32(dyn_smem);

    const int tid  = threadIdx.x;
    const int wid  = tid >> 5;
    const int lane = tid & 31;
    const int bm   = blockIdx.y * 128;
    const int bn   = blockIdx.x * 128;
    const int wm   = (wid & 1) * 64;
    const int wn   = (wid >> 1) * 32;

    const int NC = K >> 5;

    const int r0 = tid >> 3, cs = tid & 7;
    const uint32_t d0 = (uint32_t)(r0 * 128 + ((cs * 16) ^ ((r0 & 7) << 4)));
    const float* pA[4]; const float* pB[4]; bool vA[4];
#pragma unroll
    for (int it = 0; it < 4; it++) {
        int r  = r0 + 32 * it;
        int gr = bm + r;
        vA[it] = gr < M;
        pA[it] = A + (size_t)(vA[it] ? gr : 0) * K + cs * 4;
        pB[it] = B + (size_t)(bn + r) * K + cs * 4;
    }

    const int mi  = lane >> 3;
    const int r8  = lane & 7;
    const int aro = (mi & 1) * 8 + r8;
    const int akb = (mi >> 1) * 16;
    uint32_t offA[4], offB[2];
#pragma unroll
    for (int i = 0; i < 4; i++) {
        int r = wm + i * 16 + aro;
        offA[i] = (uint32_t)(r * 128 + (akb ^ ((r & 7) << 4)));
    }
#pragma unroll
    for (int j2 = 0; j2 < 2; j2++) {
        int r = wn + j2 * 16 + aro;
        offB[j2] = (uint32_t)(16384 + r * 128 + (akb ^ ((r & 7) << 4)));
    }

    float acc[4][4][4];
#pragma unroll
    for (int i = 0; i < 4; i++)
#pragma unroll
        for (int j = 0; j < 4; j++)
#pragma unroll
            for (int q = 0; q < 4; q++) acc[i][j][q] = 0.f;

    auto load_chunk = [&](uint32_t stW) {
        const uint32_t dA = sbase + stW + d0;
#pragma unroll
        for (int it = 0; it < 4; it++) {
            cpa16(dA + 4096u * it,          pA[it], vA[it]);
            cpa16(dA + 16384u + 4096u * it, pB[it], true);
            pA[it] += 32; pB[it] += 32;
        }
        asm volatile("cp.async.commit_group;" ::: "memory");
    };

    uint32_t stW = 0, stR = 0;
    load_chunk(stW); stW = STG_BYTES;
    load_chunk(stW); stW = 2 * STG_BYTES;

    uint32_t fa[2][4][4], fb[2][4][2];

    auto load_frags = [&](uint32_t st, uint32_t kb, int buf) {
#pragma unroll
        for (int i = 0; i < 4; i++)
            ldsm4(fa[buf][i][0], fa[buf][i][1], fa[buf][i][2], fa[buf][i][3],
                  st + (offA[i] ^ kb));
#pragma unroll
        for (int j2 = 0; j2 < 2; j2++) {
            uint32_t q0, q1, q2, q3;
            ldsm4(q0, q1, q2, q3, st + (offB[j2] ^ kb));
            fb[buf][j2 * 2][0]     = q0; fb[buf][j2 * 2][1]     = q2;
            fb[buf][j2 * 2 + 1][0] = q1; fb[buf][j2 * 2 + 1][1] = q3;
        }
    };
    auto do_mmas = [&](int buf) {
#pragma unroll
        for (int i = 0; i < 4; i++)
#pragma unroll
            for (int j = 0; j < 4; j++)
                mma_tf32(acc[i][j][0], acc[i][j][1], acc[i][j][2], acc[i][j][3],
                         fa[buf][i][0], fa[buf][i][1], fa[buf][i][2], fa[buf][i][3],
                         fb[buf][j][0], fb[buf][j][1]);
    };

    for (int c = 0; c < NC; c++) {
        asm volatile("cp.async.wait_group 1;" ::: "memory");
        __syncthreads();
        if (c + 2 < NC) {
            load_chunk(stW);
            stW += STG_BYTES; if (stW == 3 * STG_BYTES) stW = 0;
        }

        const uint32_t st = sbase + stR;
        stR += STG_BYTES; if (stR == 3 * STG_BYTES) stR = 0;

        load_frags(st, 0, 0);
#pragma unroll
        for (int s = 0; s < 4; s++) {
            if (s < 3) load_frags(st, (uint32_t)(32 * (s + 1)), (s + 1) & 1);
            do_mmas(s & 1);
        }
    }

    const int lm = lane >> 2, ln = (lane & 3) * 2;
#pragma unroll
    for (int i = 0; i < 4; i++) {
#pragma unroll
        for (int j = 0; j < 4; j++) {
            int m0 = bm + wm + i * 16 + lm;
            int n0 = bn + wn + j * 8 + ln;
            if (m0 < M)
                *(float2*)(C + (size_t)m0 * N + n0) =
                    make_float2(acc[i][j][0], acc[i][j][1]);
            if (m0 + 8 < M)
                *(float2*)(C + (size_t)(m0 + 8) * N + n0) =
                    make_float2(acc[i][j][2], acc[i][j][3]);
        }
    }
}

// ----------------------------------------------------------------------------
// CSR build kernels
// ----------------------------------------------------------------------------
__global__ void seti(int* __restrict__ p, int n, int v)
{
    int i = blockIdx.x * blockDim.x + threadIdx.x;
    if (i < n) p[i] = v;
}
__global__ void hist(const int* __restrict__ row, int E, int* __restrict__ cnt)
{
    int i = blockIdx.x * blockDim.x + threadIdx.x;
    if (i < E) atomicAdd(&cnt[row[i]], 1);
}
__global__ void exscan(const int* __restrict__ cnt, int* __restrict__ rp, int n)
{
    __shared__ int part[1024];
    const int t = threadIdx.x;
    const int chunk = (n + 1 + 1023) / 1024;
    const int base = t * chunk;
    int s = 0;
    for (int i = 0; i < chunk; i++) {
        int idx = base + i;
        if (idx < n) s += cnt[idx];
    }
    part[t] = s;
    __syncthreads();
    for (int off = 1; off < 1024; off <<= 1) {
        int v = (t >= off) ? part[t - off] : 0;
        __syncthreads();
        part[t] += v;
        __syncthreads();
    }
    int run = part[t] - s;
    for (int i = 0; i < chunk; i++) {
        int idx = base + i;
        if (idx <= n) {
            rp[idx] = run;
            if (idx < n) run += cnt[idx];
        }
    }
}
__global__ void copyi(const int* __restrict__ s, int* __restrict__ d, int n)
{
    int i = blockIdx.x * blockDim.x + threadIdx.x;
    if (i < n) d[i] = s[i];
}
__global__ void scatter(const int* __restrict__ row, const int* __restrict__ col,
                        const float* __restrict__ val, int E,
                        int* __restrict__ wp, int* __restrict__ colv,
                        float* __restrict__ valv)
{
    int i = blockIdx.x * blockDim.x + threadIdx.x;
    if (i >= E) return;
    int p = atomicAdd(&wp[row[i]], 1);
    colv[p] = col[i];
    valv[p] = val[i];
}

// ----------------------------------------------------------------------------
// SpMM body (shared): warp-per-row accumulate of a 512-wide row.
// ----------------------------------------------------------------------------
__device__ __forceinline__ void spmm_acc(
    const int* __restrict__ colv, const float* __restrict__ valv,
    const float* __restrict__ x, int ldx, int s, int e, int lane,
    float4& a0, float4& a1, float4& a2, float4& a3)
{
#pragma unroll 2
    for (int i = s; i < e; i++) {
        int   c = __ldg(&colv[i]);
        float v = __ldg(&valv[i]);
        const float4* xr = reinterpret_cast<const float4*>(x + (size_t)c * ldx);
        float4 t;
        t = xr[lane];
        a0.x = fmaf(v, t.x, a0.x); a0.y = fmaf(v, t.y, a0.y);
        a0.z = fmaf(v, t.z, a0.z); a0.w = fmaf(v, t.w, a0.w);
        t = xr[lane + 32];
        a1.x = fmaf(v, t.x, a1.x); a1.y = fmaf(v, t.y, a1.y);
        a1.z = fmaf(v, t.z, a1.z); a1.w = fmaf(v, t.w, a1.w);
        t = xr[lane + 64];
        a2.x = fmaf(v, t.x, a2.x); a2.y = fmaf(v, t.y, a2.y);
        a2.z = fmaf(v, t.z, a2.z); a2.w = fmaf(v, t.w, a2.w);
        t = xr[lane + 96];
        a3.x = fmaf(v, t.x, a3.x); a3.y = fmaf(v, t.y, a3.y);
        a3.z = fmaf(v, t.z, a3.z); a3.w = fmaf(v, t.w, a3.w);
    }
}

// generic pass (partials / layer-3 accumulation into d_out)
__global__ __launch_bounds__(256) void spmm_csr(
    const int* __restrict__ rp, const int* __restrict__ colv,
    const float* __restrict__ valv, const float* __restrict__ x, int ldx,
    float* __restrict__ out, int nrows, int ldo, int beta)
{
    int row  = (blockIdx.x * blockDim.x + threadIdx.x) >> 5;
    int lane = threadIdx.x & 31;
    if (row >= nrows) return;

    float4 a0 = make_float4(0.f, 0.f, 0.f, 0.f), a1 = a0, a2 = a0, a3 = a0;
    spmm_acc(colv, valv, x, ldx, rp[row], rp[row + 1], lane, a0, a1, a2, a3);

    float4* o = reinterpret_cast<float4*>(out + (size_t)row * ldo);
    if (beta) {
        float4 t;
        t = o[lane];      a0.x += t.x; a0.y += t.y; a0.z += t.z; a0.w += t.w;
        t = o[lane + 32]; a1.x += t.x; a1.y += t.y; a1.z += t.z; a1.w += t.w;
        t = o[lane + 64]; a2.x += t.x; a2.y += t.y; a2.z += t.z; a2.w += t.w;
        t = o[lane + 96]; a3.x += t.x; a3.y += t.y; a3.z += t.z; a3.w += t.w;
    }
    o[lane]      = a0;
    o[lane + 32] = a1;
    o[lane + 64] = a2;
    o[lane + 96] = a3;
}

// final layer-1 pass: acc + partial(et) -> relu -> d_out dual copy + et=tf32(.)
__global__ __launch_bounds__(256) void spmm_fin_dual(
    const int* __restrict__ rp, const int* __restrict__ colv,
    const float* __restrict__ valv, const float* __restrict__ x, int ldx,
    float* __restrict__ et, float* __restrict__ outbase, int nrows)
{
    int row  = (blockIdx.x * blockDim.x + threadIdx.x) >> 5;
    int lane = threadIdx.x & 31;
    if (row >= nrows) return;

    float4 a0 = make_float4(0.f, 0.f, 0.f, 0.f), a1 = a0, a2 = a0, a3 = a0;
    spmm_acc(colv, valv, x, ldx, rp[row], rp[row + 1], lane, a0, a1, a2, a3);

    float4* pp = reinterpret_cast<float4*>(et + (size_t)row * KH);
    float4 t;
    t = pp[lane];      a0.x += t.x; a0.y += t.y; a0.z += t.z; a0.w += t.w;
    t = pp[lane + 32]; a1.x += t.x; a1.y += t.y; a1.z += t.z; a1.w += t.w;
    t = pp[lane + 64]; a2.x += t.x; a2.y += t.y; a2.z += t.z; a2.w += t.w;
    t = pp[lane + 96]; a3.x += t.x; a3.y += t.y; a3.z += t.z; a3.w += t.w;

    a0.x = fmaxf(a0.x, 0.f); a0.y = fmaxf(a0.y, 0.f); a0.z = fmaxf(a0.z, 0.f); a0.w = fmaxf(a0.w, 0.f);
    a1.x = fmaxf(a1.x, 0.f); a1.y = fmaxf(a1.y, 0.f); a1.z = fmaxf(a1.z, 0.f); a1.w = fmaxf(a1.w, 0.f);
    a2.x = fmaxf(a2.x, 0.f); a2.y = fmaxf(a2.y, 0.f); a2.z = fmaxf(a2.z, 0.f); a2.w = fmaxf(a2.w, 0.f);
    a3.x = fmaxf(a3.x, 0.f); a3.y = fmaxf(a3.y, 0.f); a3.z = fmaxf(a3.z, 0.f); a3.w = fmaxf(a3.w, 0.f);

    float4* o = reinterpret_cast<float4*>(outbase + (size_t)row * LDO);
    o[lane]       = a0; o[lane + 32]  = a1; o[lane + 64]  = a2; o[lane + 96]  = a3;
    o[lane + 128] = a0; o[lane + 160] = a1; o[lane + 192] = a2; o[lane + 224] = a3;

    a0.x = tf32r(a0.x); a0.y = tf32r(a0.y); a0.z = tf32r(a0.z); a0.w = tf32r(a0.w);
    a1.x = tf32r(a1.x); a1.y = tf32r(a1.y); a1.z = tf32r(a1.z); a1.w = tf32r(a1.w);
    a2.x = tf32r(a2.x); a2.y = tf32r(a2.y); a2.z = tf32r(a2.z); a2.w = tf32r(a2.w);
    a3.x = tf32r(a3.x); a3.y = tf32r(a3.y); a3.z = tf32r(a3.z); a3.w = tf32r(a3.w);
    pp[lane] = a0; pp[lane + 32] = a1; pp[lane + 64] = a2; pp[lane + 96] = a3;
}

// final layer-2 pass: acc + partial(et) -> relu -> et=tf32(.)
__global__ __launch_bounds__(256) void spmm_fin_t(
    const int* __restrict__ rp, const int* __restrict__ colv,
    const float* __restrict__ valv, const float* __restrict__ x, int ldx,
    float* __restrict__ et, int nrows)
{
    int row  = (blockIdx.x * blockDim.x + threadIdx.x) >> 5;
    int lane = threadIdx.x & 31;
    if (row >= nrows) return;

    float4 a0 = make_float4(0.f, 0.f, 0.f, 0.f), a1 = a0, a2 = a0, a3 = a0;
    spmm_acc(colv, valv, x, ldx, rp[row], rp[row + 1], lane, a0, a1, a2, a3);

    float4* pp = reinterpret_cast<float4*>(et + (size_t)row * KH);
    float4 t;
    t = pp[lane];      a0.x += t.x; a0.y += t.y; a0.z += t.z; a0.w += t.w;
    t = pp[lane + 32]; a1.x += t.x; a1.y += t.y; a1.z += t.z; a1.w += t.w;
    t = pp[lane + 64]; a2.x += t.x; a2.y += t.y; a2.z += t.z; a2.w += t.w;
    t = pp[lane + 96]; a3.x += t.x; a3.y += t.y; a3.z += t.z; a3.w += t.w;

    a0.x = tf32r(fmaxf(a0.x, 0.f)); a0.y = tf32r(fmaxf(a0.y, 0.f));
    a0.z = tf32r(fmaxf(a0.z, 0.f)); a0.w = tf32r(fmaxf(a0.w, 0.f));
    a1.x = tf32r(fmaxf(a1.x, 0.f)); a1.y = tf32r(fmaxf(a1.y, 0.f));
    a1.z = tf32r(fmaxf(a1.z, 0.f)); a1.w = tf32r(fmaxf(a1.w, 0.f));
    a2.x = tf32r(fmaxf(a2.x, 0.f)); a2.y = tf32r(fmaxf(a2.y, 0.f));
    a2.z = tf32r(fmaxf(a2.z, 0.f)); a2.w = tf32r(fmaxf(a2.w, 0.f));
    a3.x = tf32r(fmaxf(a3.x, 0.f)); a3.y = tf32r(fmaxf(a3.y, 0.f));
    a3.z = tf32r(fmaxf(a3.z, 0.f)); a3.w = tf32r(fmaxf(a3.w, 0.f));
    pp[lane] = a0; pp[lane + 32] = a1; pp[lane + 64] = a2; pp[lane + 96] = a3;
}

// ----------------------------------------------------------------------------
// Converters
// ----------------------------------------------------------------------------
__global__ void tf32_round4(const float* __restrict__ x, float* __restrict__ y, size_t n4)
{
    size_t i = blockIdx.x * (size_t)blockDim.x + threadIdx.x;
    if (i >= n4) return;
    float4 t = reinterpret_cast<const float4*>(x)[i];
    t.x = tf32r(t.x); t.y = tf32r(t.y); t.z = tf32r(t.z); t.w = tf32r(t.w);
    reinterpret_cast<float4*>(y)[i] = t;
}

__global__ void wt_t(const float* __restrict__ W, float* __restrict__ T, int K)
{
    __shared__ float t[32][33];
    int kb = blockIdx.x * 32, nb = blockIdx.y * 32;
    int x = threadIdx.x, y = threadIdx.y;
#pragma unroll
    for (int i = 0; i < 32; i += 8)
        t[y + i][x] = W[(size_t)(kb + y + i) * KH + nb + x];
    __syncthreads();
#pragma unroll
    for (int i = 0; i < 32; i += 8)
        T[(size_t)(nb + y + i) * K + kb + x] = tf32r(t[x][y + i]);
}

// ----------------------------------------------------------------------------
// Host orchestration
// ----------------------------------------------------------------------------
extern "C" void kernel_launch(void* const* d_in, const int* in_sizes, int n_in,
                              void* d_out, int out_size)
{
    const float* feat0 = (const float*)d_in[0];
    const float* feat1 = (const float*)d_in[1];

    const int*   a_row[5]; const int* a_col[5]; const float* a_val[5]; int Ecnt[5];
    for (int i = 0; i < 5; i++) {
        a_row[i] = (const int*)d_in[2 + 3 * i];
        a_col[i] = (const int*)d_in[3 + 3 * i];
        a_val[i] = (const float*)d_in[4 + 3 * i];
        Ecnt[i]  = in_sizes[2 + 3 * i];
    }
    const int nrows_rel[5] = {KN0, KN0, KN1, KN1, KN1};
    const float* W[3][5];
    for (int r = 0; r < 5; r++)
        for (int l = 0; l < 3; l++)
            W[l][r] = (const float*)d_in[17 + 3 * r + l];

    float *tmpA, *tmpB;
    float *f0t, *f1t, *e00t, *e01t, *e20t, *e21t, *wt;
    int *rp, *wp, *colv; float *valv;
    {
        void* p;
        cudaGetSymbolAddress(&p, g_tmpA); tmpA = (float*)p;
        cudaGetSymbolAddress(&p, g_tmpB); tmpB = (float*)p;
        cudaGetSymbolAddress(&p, g_f0t);  f0t  = (float*)p;
        cudaGetSymbolAddress(&p, g_f1t);  f1t  = (float*)p;
        cudaGetSymbolAddress(&p, g_e00t); e00t = (float*)p;
        cudaGetSymbolAddress(&p, g_e01t); e01t = (float*)p;
        cudaGetSymbolAddress(&p, g_e20t); e20t = (float*)p;
        cudaGetSymbolAddress(&p, g_e21t); e21t = (float*)p;
        cudaGetSymbolAddress(&p, g_wt);   wt   = (float*)p;
        cudaGetSymbolAddress(&p, g_rp);   rp   = (int*)p;
        cudaGetSymbolAddress(&p, g_wp);   wp   = (int*)p;
        cudaGetSymbolAddress(&p, g_colv); colv = (int*)p;
        cudaGetSymbolAddress(&p, g_valv); valv = (float*)p;
    }
    float* out = (float*)d_out;

    const size_t WA_off[3] = {0, 2621440, 3932160};
    const size_t WB_off[3] = {1048576, 3145728, 4456448};
    const int    Kl[3]     = {KF, KH, KH};

    size_t eoff[5]; size_t acc_e = 0;
    for (int r = 0; r < 5; r++) { eoff[r] = acc_e; acc_e += (size_t)Ecnt[r]; }

    cudaFuncSetAttribute(gemm_tf32, cudaFuncAttributeMaxDynamicSharedMemorySize, GEMM_SMEM);

    auto do_wt = [&](int l, int rel, float* dst_base, int rowoff) {
        int K = Kl[l];
        wt_t<<<dim3(K / 32, KH / 32), dim3(32, 8)>>>(W[l][rel],
                                                     dst_base + (size_t)rowoff * K, K);
    };
    auto gemm = [&](const float* A, const float* B, float* C, int M, int N, int K) {
        dim3 grid(N / 128, (M + 127) / 128);
        gemm_tf32<<<grid, 256, GEMM_SMEM>>>(A, B, C, M, N, K);
    };
    auto build_csr = [&](int r) {
        int n = nrows_rel[r], E = Ecnt[r];
        int* rpr = rp + r * RPN;
        int* wpr = wp + r * RPN;
        seti<<<(n + 255) / 256, 256>>>(wpr, n, 0);
        hist<<<(E + 255) / 256, 256>>>(a_row[r], E, wpr);
        exscan<<<1, 1024>>>(wpr, rpr, n);
        copyi<<<(n + 255) / 256, 256>>>(rpr, wpr, n);
        scatter<<<(E + 255) / 256, 256>>>(a_row[r], a_col[r], a_val[r], E,
                                          wpr, colv + eoff[r], valv + eoff[r]);
    };
    auto xsrc = [&](int rel, const float*& x, int& ldx) {
        switch (rel) {
            case 0: x = tmpA;         ldx = 1024; break;
            case 1: x = tmpB;         ldx = 1536; break;
            case 2: x = tmpA + 512;   ldx = 1024; break;
            case 3: x = tmpB + 512;   ldx = 1536; break;
            default: x = tmpB + 1024; ldx = 1536; break;
        }
    };
    auto spmm = [&](int rel, float* dst, int ldo, int beta) {
        int n = nrows_rel[rel];
        const float* x; int ldx; xsrc(rel, x, ldx);
        spmm_csr<<<(n * 32 + 255) / 256, 256>>>(rp + rel * RPN, colv + eoff[rel],
                                                valv + eoff[rel], x, ldx, dst, n, ldo, beta);
    };
    auto spmm_fdual = [&](int rel, float* et, float* ob) {
        int n = nrows_rel[rel];
        const float* x; int ldx; xsrc(rel, x, ldx);
        spmm_fin_dual<<<(n * 32 + 255) / 256, 256>>>(rp + rel * RPN, colv + eoff[rel],
                                                     valv + eoff[rel], x, ldx, et, ob, n);
    };
    auto spmm_ft = [&](int rel, float* et) {
        int n = nrows_rel[rel];
        const float* x; int ldx; xsrc(rel, x, ldx);
        spmm_fin_t<<<(n * 32 + 255) / 256, 256>>>(rp + rel * RPN, colv + eoff[rel],
                                                  valv + eoff[rel], x, ldx, et, n);
    };
    auto round_to = [&](const float* s, float* d, size_t nelem) {
        size_t n4 = nelem / 4;
        tf32_round4<<<(unsigned)((n4 + 255) / 256), 256>>>(s, d, n4);
    };

    float* wA1 = wt + WA_off[0];
    float* wB1 = wt + WB_off[0];

    // Launch order: #4 is the big fused M=30000/N=1024/K=1024 gemm (profiled).
    do_wt(0, 0, wA1, 0);                              // 1
    do_wt(0, 2, wA1, 512);                            // 2
    round_to(feat0, f0t, (size_t)KN0 * KF);           // 3
    gemm(f0t, wA1, tmpA, KN0, 1024, KF);              // 4  <- profiled
    round_to(feat1, f1t, (size_t)KN1 * KF);           // 5
    do_wt(0, 1, wB1, 0);
    do_wt(0, 3, wB1, 512);
    do_wt(0, 4, wB1, 1024);
    gemm(f1t, wB1, tmpB, KN1, 1536, KF);
    for (int r = 0; r < 5; r++) build_csr(r);

    // ---------------- Layer 1: partial -> final (fused relu/out/round) -------
    spmm(0, e00t, KH, 0);
    spmm_fdual(1, e00t, out);
    spmm(2, e01t, KH, 0);
    spmm(3, e01t, KH, 1);
    spmm_fdual(4, e01t, out + (size_t)KN0 * LDO);

    for (int l = 1; l < 3; l++) {
        do_wt(l, 0, wt + WA_off[l], 0);
        do_wt(l, 2, wt + WA_off[l], 512);
        do_wt(l, 1, wt + WB_off[l], 0);
        do_wt(l, 3, wt + WB_off[l], 512);
        do_wt(l, 4, wt + WB_off[l], 1024);
    }

    // ---------------- Layer 2 ----------------
    gemm(e00t, wt + WA_off[1], tmpA, KN0, 1024, KH);
    gemm(e01t, wt + WB_off[1], tmpB, KN1, 1536, KH);
    spmm(0, e20t, KH, 0);
    spmm_ft(1, e20t);
    spmm(2, e21t, KH, 0);
    spmm(3, e21t, KH, 1);
    spmm_ft(4, e21t);

    // ---------------- Layer 3 (into d_out cols 1024:1536) ----------------
    gemm(e20t, wt + WA_off[2], tmpA, KN0, 1024, KH);
    gemm(e21t, wt + WB_off[2], tmpB, KN1, 1536, KH);
    float* out3_t0 = out + 1024;
    float* out3_t1 = out + (size_t)KN0 * LDO + 1024;
    spmm(0, out3_t0, LDO, 0); spmm(1, out3_t0, LDO, 1);
    spmm(2, out3_t1, LDO, 0); spmm(3, out3_t1, LDO, 1); spmm(4, out3_t1, LDO, 1);
}

// round 14
// speedup vs baseline: 1.9487x; 1.0059x over previous
#include <cuda_runtime.h>
#include <cuda_bf16.h>
#include <cstdint>
#include <cstddef>

// ============================================================================
// DecagonModel — R14: R13 + multi-relation SpMM (one kernel per destination;
// partial-sum gmem roundtrips eliminated; 15 SpMM launches -> 6).
// ============================================================================

#define KN0 30000
#define KN1 6000
#define KF  1024
#define KH  512
#define LDO 1536
#define ECAP 2100000
#define RPN  30001

// ---------------- device-global scratch -------------------------------------
__device__ float g_tmpA[KN0 * 1024];
__device__ float g_tmpB[KN1 * 1536];

__device__ float g_f0t[KN0 * KF];
__device__ float g_f1t[KN1 * KF];
__device__ float g_e00t[KN0 * KH];
__device__ float g_e01t[KN1 * KH];
__device__ float g_e20t[KN0 * KH];
__device__ float g_e21t[KN1 * KH];

#define WT_TOTAL 5242880
__device__ float g_wt[WT_TOTAL];

__device__ int   g_rp[5 * RPN];
__device__ int   g_wp[5 * RPN];
__device__ int   g_colv[ECAP];
__device__ float g_valv[ECAP];

// ---------------- helpers ---------------------------------------------------
__device__ __forceinline__ uint32_t smem_u32(const void* p) {
    uint32_t a;
    asm("{ .reg .u64 t; cvta.to.shared.u64 t, %1; cvt.u32.u64 %0, t; }"
        : "=r"(a) : "l"(p));
    return a;
}
__device__ __forceinline__ void cpa16(uint32_t dst, const void* src, bool v) {
    asm volatile("cp.async.cg.shared.global [%0], [%1], 16, %2;"
                 :: "r"(dst), "l"(src), "r"(v ? 16 : 0) : "memory");
}
__device__ __forceinline__ void ldsm4(uint32_t& r0, uint32_t& r1, uint32_t& r2,
                                      uint32_t& r3, uint32_t addr) {
    asm volatile("ldmatrix.sync.aligned.m8n8.x4.shared.b16 {%0,%1,%2,%3}, [%4];"
                 : "=r"(r0), "=r"(r1), "=r"(r2), "=r"(r3) : "r"(addr));
}
__device__ __forceinline__ void mma_tf32(float& c0, float& c1, float& c2, float& c3,
                                         uint32_t a0, uint32_t a1, uint32_t a2, uint32_t a3,
                                         uint32_t b0, uint32_t b1) {
    asm volatile(
        "mma.sync.aligned.m16n8k8.row.col.f32.tf32.tf32.f32 "
        "{%0,%1,%2,%3}, {%4,%5,%6,%7}, {%8,%9}, {%0,%1,%2,%3};"
        : "+f"(c0), "+f"(c1), "+f"(c2), "+f"(c3)
        : "r"(a0), "r"(a1), "r"(a2), "r"(a3), "r"(b0), "r"(b1));
}
__device__ __forceinline__ float tf32r(float x) {
    uint32_t r;
    asm("cvt.rna.tf32.f32 %0, %1;" : "=r"(r) : "f"(x));
    return __uint_as_float(r);
}

// ----------------------------------------------------------------------------
// TF32 GEMM (R12 mainloop: hoisted addressing + fragment double-buffering)
// ----------------------------------------------------------------------------
#define STG_BYTES 32768u
#define GEMM_SMEM (3 * STG_BYTES)

__global__ __launch_bounds__(256) void gemm_tf32(
    const float* __restrict__ A, const float* __restrict__ B,
    float* __restrict__ C, int M, int N, int K)
{
    extern __shared__ char dyn_smem[];
    const uint32_t sbase = smem_u32(dyn_smem);

    const int tid  = threadIdx.x;
    const int wid  = tid >> 5;
    const int lane = tid & 31;
    const int bm   = blockIdx.y * 128;
    const int bn   = blockIdx.x * 128;
    const int wm   = (wid & 1) * 64;
    const int wn   = (wid >> 1) * 32;

    const int NC = K >> 5;

    const int r0 = tid >> 3, cs = tid & 7;
    const uint32_t d0 = (uint32_t)(r0 * 128 + ((cs * 16) ^ ((r0 & 7) << 4)));
    const float* pA[4]; const float* pB[4]; bool vA[4];
#pragma unroll
    for (int it = 0; it < 4; it++) {
        int r  = r0 + 32 * it;
        int gr = bm + r;
        vA[it] = gr < M;
        pA[it] = A + (size_t)(vA[it] ? gr : 0) * K + cs * 4;
        pB[it] = B + (size_t)(bn + r) * K + cs * 4;
    }

    const int mi  = lane >> 3;
    const int r8  = lane & 7;
    const int aro = (mi & 1) * 8 + r8;
    const int akb = (mi >> 1) * 16;
    uint32_t offA[4], offB[2];
#pragma unroll
    for (int i = 0; i < 4; i++) {
        int r = wm + i * 16 + aro;
        offA[i] = (uint32_t)(r * 128 + (akb ^ ((r & 7) << 4)));
    }
#pragma unroll
    for (int j2 = 0; j2 < 2; j2++) {
        int r = wn + j2 * 16 + aro;
        offB[j2] = (uint32_t)(16384 + r * 128 + (akb ^ ((r & 7) << 4)));
    }

    float acc[4][4][4];
#pragma unroll
    for (int i = 0; i < 4; i++)
#pragma unroll
        for (int j = 0; j < 4; j++)
#pragma unroll
            for (int q = 0; q < 4; q++) acc[i][j][q] = 0.f;

    auto load_chunk = [&](uint32_t stW) {
        const uint32_t dA = sbase + stW + d0;
#pragma unroll
        for (int it = 0; it < 4; it++) {
            cpa16(dA + 4096u * it,          pA[it], vA[it]);
            cpa16(dA + 16384u + 4096u * it, pB[it], true);
            pA[it] += 32; pB[it] += 32;
        }
        asm volatile("cp.async.commit_group;" ::: "memory");
    };

    uint32_t stW = 0, stR = 0;
    load_chunk(stW); stW = STG_BYTES;
    load_chunk(stW); stW = 2 * STG_BYTES;

    uint32_t fa[2][4][4], fb[2][4][2];

    auto load_frags = [&](uint32_t st, uint32_t kb, int buf) {
#pragma unroll
        for (int i = 0; i < 4; i++)
            ldsm4(fa[buf][i][0], fa[buf][i][1], fa[buf][i][2], fa[buf][i][3],
                  st + (offA[i] ^ kb));
#pragma unroll
        for (int j2 = 0; j2 < 2; j2++) {
            uint32_t q0, q1, q2, q3;
            ldsm4(q0, q1, q2, q3, st + (offB[j2] ^ kb));
            fb[buf][j2 * 2][0]     = q0; fb[buf][j2 * 2][1]     = q2;
            fb[buf][j2 * 2 + 1][0] = q1; fb[buf][j2 * 2 + 1][1] = q3;
        }
    };
    auto do_mmas = [&](int buf) {
#pragma unroll
        for (int i = 0; i < 4; i++)
#pragma unroll
            for (int j = 0; j < 4; j++)
                mma_tf32(acc[i][j][0], acc[i][j][1], acc[i][j][2], acc[i][j][3],
                         fa[buf][i][0], fa[buf][i][1], fa[buf][i][2], fa[buf][i][3],
                         fb[buf][j][0], fb[buf][j][1]);
    };

    for (int c = 0; c < NC; c++) {
        asm volatile("cp.async.wait_group 1;" ::: "memory");
        __syncthreads();
        if (c + 2 < NC) {
            load_chunk(stW);
            stW += STG_BYTES; if (stW == 3 * STG_BYTES) stW = 0;
        }

        const uint32_t st = sbase + stR;
        stR += STG_BYTES; if (stR == 3 * STG_BYTES) stR = 0;

        load_frags(st, 0, 0);
#pragma unroll
        for (int s = 0; s < 4; s++) {
            if (s < 3) load_frags(st, (uint32_t)(32 * (s + 1)), (s + 1) & 1);
            do_mmas(s & 1);
        }
    }

    const int lm = lane >> 2, ln = (lane & 3) * 2;
#pragma unroll
    for (int i = 0; i < 4; i++) {
#pragma unroll
        for (int j = 0; j < 4; j++) {
            int m0 = bm + wm + i * 16 + lm;
            int n0 = bn + wn + j * 8 + ln;
            if (m0 < M)
                *(float2*)(C + (size_t)m0 * N + n0) =
                    make_float2(acc[i][j][0], acc[i][j][1]);
            if (m0 + 8 < M)
                *(float2*)(C + (size_t)(m0 + 8) * N + n0) =
                    make_float2(acc[i][j][2], acc[i][j][3]);
        }
    }
}

// ----------------------------------------------------------------------------
// CSR build kernels
// ----------------------------------------------------------------------------
__global__ void seti(int* __restrict__ p, int n, int v)
{
    int i = blockIdx.x * blockDim.x + threadIdx.x;
    if (i < n) p[i] = v;
}
__global__ void hist(const int* __restrict__ row, int E, int* __restrict__ cnt)
{
    int i = blockIdx.x * blockDim.x + threadIdx.x;
    if (i < E) atomicAdd(&cnt[row[i]], 1);
}
__global__ void exscan(const int* __restrict__ cnt, int* __restrict__ rp, int n)
{
    __shared__ int part[1024];
    const int t = threadIdx.x;
    const int chunk = (n + 1 + 1023) / 1024;
    const int base = t * chunk;
    int s = 0;
    for (int i = 0; i < chunk; i++) {
        int idx = base + i;
        if (idx < n) s += cnt[idx];
    }
    part[t] = s;
    __syncthreads();
    for (int off = 1; off < 1024; off <<= 1) {
        int v = (t >= off) ? part[t - off] : 0;
        __syncthreads();
        part[t] += v;
        __syncthreads();
    }
    int run = part[t] - s;
    for (int i = 0; i < chunk; i++) {
        int idx = base + i;
        if (idx <= n) {
            rp[idx] = run;
            if (idx < n) run += cnt[idx];
        }
    }
}
__global__ void copyi(const int* __restrict__ s, int* __restrict__ d, int n)
{
    int i = blockIdx.x * blockDim.x + threadIdx.x;
    if (i < n) d[i] = s[i];
}
__global__ void scatter(const int* __restrict__ row, const int* __restrict__ col,
                        const float* __restrict__ val, int E,
                        int* __restrict__ wp, int* __restrict__ colv,
                        float* __restrict__ valv)
{
    int i = blockIdx.x * blockDim.x + threadIdx.x;
    if (i >= E) return;
    int p = atomicAdd(&wp[row[i]], 1);
    colv[p] = col[i];
    valv[p] = val[i];
}

// ----------------------------------------------------------------------------
// Multi-relation SpMM: one warp per destination row; walks up to 3 CSRs.
// MODE 0: raw sum -> dst (stride ldo)          [layer 3 -> d_out cols]
// MODE 1: relu -> out2 dual copy (LDO) + tf32 -> dst (KH)   [layer 1]
// MODE 2: relu+tf32 -> dst (KH)                [layer 2]
// ----------------------------------------------------------------------------
struct RelSrc {
    const int*   rp;
    const int*   colv;
    const float* valv;
    const float* x;
    int          ldx;
};

__device__ __forceinline__ void spmm_acc(
    const RelSrc& R, int row, int lane,
    float4& a0, float4& a1, float4& a2, float4& a3)
{
    int s = __ldg(&R.rp[row]), e = __ldg(&R.rp[row + 1]);
#pragma unroll 2
    for (int i = s; i < e; i++) {
        int   c = __ldg(&R.colv[i]);
        float v = __ldg(&R.valv[i]);
        const float4* xr = reinterpret_cast<const float4*>(R.x + (size_t)c * R.ldx);
        float4 t;
        t = xr[lane];
        a0.x = fmaf(v, t.x, a0.x); a0.y = fmaf(v, t.y, a0.y);
        a0.z = fmaf(v, t.z, a0.z); a0.w = fmaf(v, t.w, a0.w);
        t = xr[lane + 32];
        a1.x = fmaf(v, t.x, a1.x); a1.y = fmaf(v, t.y, a1.y);
        a1.z = fmaf(v, t.z, a1.z); a1.w = fmaf(v, t.w, a1.w);
        t = xr[lane + 64];
        a2.x = fmaf(v, t.x, a2.x); a2.y = fmaf(v, t.y, a2.y);
        a2.z = fmaf(v, t.z, a2.z); a2.w = fmaf(v, t.w, a2.w);
        t = xr[lane + 96];
        a3.x = fmaf(v, t.x, a3.x); a3.y = fmaf(v, t.y, a3.y);
        a3.z = fmaf(v, t.z, a3.z); a3.w = fmaf(v, t.w, a3.w);
    }
}

template <int MODE, int NREL>
__global__ __launch_bounds__(256) void spmm_multi(
    RelSrc r0, RelSrc r1, RelSrc r2,
    float* __restrict__ dst, float* __restrict__ out2, int nrows, int ldo)
{
    int row  = (blockIdx.x * blockDim.x + threadIdx.x) >> 5;
    int lane = threadIdx.x & 31;
    if (row >= nrows) return;

    float4 a0 = make_float4(0.f, 0.f, 0.f, 0.f), a1 = a0, a2 = a0, a3 = a0;
    spmm_acc(r0, row, lane, a0, a1, a2, a3);
    if (NREL >= 2) spmm_acc(r1, row, lane, a0, a1, a2, a3);
    if (NREL >= 3) spmm_acc(r2, row, lane, a0, a1, a2, a3);

    if (MODE == 0) {
        float4* o = reinterpret_cast<float4*>(dst + (size_t)row * ldo);
        o[lane] = a0; o[lane + 32] = a1; o[lane + 64] = a2; o[lane + 96] = a3;
        return;
    }

    // relu
    a0.x = fmaxf(a0.x, 0.f); a0.y = fmaxf(a0.y, 0.f); a0.z = fmaxf(a0.z, 0.f); a0.w = fmaxf(a0.w, 0.f);
    a1.x = fmaxf(a1.x, 0.f); a1.y = fmaxf(a1.y, 0.f); a1.z = fmaxf(a1.z, 0.f); a1.w = fmaxf(a1.w, 0.f);
    a2.x = fmaxf(a2.x, 0.f); a2.y = fmaxf(a2.y, 0.f); a2.z = fmaxf(a2.z, 0.f); a2.w = fmaxf(a2.w, 0.f);
    a3.x = fmaxf(a3.x, 0.f); a3.y = fmaxf(a3.y, 0.f); a3.z = fmaxf(a3.z, 0.f); a3.w = fmaxf(a3.w, 0.f);

    if (MODE == 1) {
        float4* o = reinterpret_cast<float4*>(out2 + (size_t)row * LDO);
        o[lane]       = a0; o[lane + 32]  = a1; o[lane + 64]  = a2; o[lane + 96]  = a3;
        o[lane + 128] = a0; o[lane + 160] = a1; o[lane + 192] = a2; o[lane + 224] = a3;
    }

    a0.x = tf32r(a0.x); a0.y = tf32r(a0.y); a0.z = tf32r(a0.z); a0.w = tf32r(a0.w);
    a1.x = tf32r(a1.x); a1.y = tf32r(a1.y); a1.z = tf32r(a1.z); a1.w = tf32r(a1.w);
    a2.x = tf32r(a2.x); a2.y = tf32r(a2.y); a2.z = tf32r(a2.z); a2.w = tf32r(a2.w);
    a3.x = tf32r(a3.x); a3.y = tf32r(a3.y); a3.z = tf32r(a3.z); a3.w = tf32r(a3.w);
    float4* p = reinterpret_cast<float4*>(dst + (size_t)row * KH);
    p[lane] = a0; p[lane + 32] = a1; p[lane + 64] = a2; p[lane + 96] = a3;
}

// ----------------------------------------------------------------------------
// Converters
// ----------------------------------------------------------------------------
__global__ void tf32_round4(const float* __restrict__ x, float* __restrict__ y, size_t n4)
{
    size_t i = blockIdx.x * (size_t)blockDim.x + threadIdx.x;
    if (i >= n4) return;
    float4 t = reinterpret_cast<const float4*>(x)[i];
    t.x = tf32r(t.x); t.y = tf32r(t.y); t.z = tf32r(t.z); t.w = tf32r(t.w);
    reinterpret_cast<float4*>(y)[i] = t;
}

__global__ void wt_t(const float* __restrict__ W, float* __restrict__ T, int K)
{
    __shared__ float t[32][33];
    int kb = blockIdx.x * 32, nb = blockIdx.y * 32;
    int x = threadIdx.x, y = threadIdx.y;
#pragma unroll
    for (int i = 0; i < 32; i += 8)
        t[y + i][x] = W[(size_t)(kb + y + i) * KH + nb + x];
    __syncthreads();
#pragma unroll
    for (int i = 0; i < 32; i += 8)
        T[(size_t)(nb + y + i) * K + kb + x] = tf32r(t[x][y + i]);
}

// ----------------------------------------------------------------------------
// Host orchestration
// ----------------------------------------------------------------------------
extern "C" void kernel_launch(void* const* d_in, const int* in_sizes, int n_in,
                              void* d_out, int out_size)
{
    const float* feat0 = (const float*)d_in[0];
    const float* feat1 = (const float*)d_in[1];

    const int*   a_row[5]; const int* a_col[5]; const float* a_val[5]; int Ecnt[5];
    for (int i = 0; i < 5; i++) {
        a_row[i] = (const int*)d_in[2 + 3 * i];
        a_col[i] = (const int*)d_in[3 + 3 * i];
        a_val[i] = (const float*)d_in[4 + 3 * i];
        Ecnt[i]  = in_sizes[2 + 3 * i];
    }
    const int nrows_rel[5] = {KN0, KN0, KN1, KN1, KN1};
    const float* W[3][5];
    for (int r = 0; r < 5; r++)
        for (int l = 0; l < 3; l++)
            W[l][r] = (const float*)d_in[17 + 3 * r + l];

    float *tmpA, *tmpB;
    float *f0t, *f1t, *e00t, *e01t, *e20t, *e21t, *wt;
    int *rp, *wp, *colv; float *valv;
    {
        void* p;
        cudaGetSymbolAddress(&p, g_tmpA); tmpA = (float*)p;
        cudaGetSymbolAddress(&p, g_tmpB); tmpB = (float*)p;
        cudaGetSymbolAddress(&p, g_f0t);  f0t  = (float*)p;
        cudaGetSymbolAddress(&p, g_f1t);  f1t  = (float*)p;
        cudaGetSymbolAddress(&p, g_e00t); e00t = (float*)p;
        cudaGetSymbolAddress(&p, g_e01t); e01t = (float*)p;
        cudaGetSymbolAddress(&p, g_e20t); e20t = (float*)p;
        cudaGetSymbolAddress(&p, g_e21t); e21t = (float*)p;
        cudaGetSymbolAddress(&p, g_wt);   wt   = (float*)p;
        cudaGetSymbolAddress(&p, g_rp);   rp   = (int*)p;
        cudaGetSymbolAddress(&p, g_wp);   wp   = (int*)p;
        cudaGetSymbolAddress(&p, g_colv); colv = (int*)p;
        cudaGetSymbolAddress(&p, g_valv); valv = (float*)p;
    }
    float* out = (float*)d_out;

    const size_t WA_off[3] = {0, 2621440, 3932160};
    const size_t WB_off[3] = {1048576, 3145728, 4456448};
    const int    Kl[3]     = {KF, KH, KH};

    size_t eoff[5]; size_t acc_e = 0;
    for (int r = 0; r < 5; r++) { eoff[r] = acc_e; acc_e += (size_t)Ecnt[r]; }

    cudaFuncSetAttribute(gemm_tf32, cudaFuncAttributeMaxDynamicSharedMemorySize, GEMM_SMEM);

    auto do_wt = [&](int l, int rel, float* dst_base, int rowoff) {
        int K = Kl[l];
        wt_t<<<dim3(K / 32, KH / 32), dim3(32, 8)>>>(W[l][rel],
                                                     dst_base + (size_t)rowoff * K, K);
    };
    auto gemm = [&](const float* A, const float* B, float* C, int M, int N, int K) {
        dim3 grid(N / 128, (M + 127) / 128);
        gemm_tf32<<<grid, 256, GEMM_SMEM>>>(A, B, C, M, N, K);
    };
    auto build_csr = [&](int r) {
        int n = nrows_rel[r], E = Ecnt[r];
        int* rpr = rp + r * RPN;
        int* wpr = wp + r * RPN;
        seti<<<(n + 255) / 256, 256>>>(wpr, n, 0);
        hist<<<(E + 255) / 256, 256>>>(a_row[r], E, wpr);
        exscan<<<1, 1024>>>(wpr, rpr, n);
        copyi<<<(n + 255) / 256, 256>>>(rpr, wpr, n);
        scatter<<<(E + 255) / 256, 256>>>(a_row[r], a_col[r], a_val[r], E,
                                          wpr, colv + eoff[r], valv + eoff[r]);
    };
    auto mkrel = [&](int rel) {
        RelSrc R;
        R.rp   = rp + rel * RPN;
        R.colv = colv + eoff[rel];
        R.valv = valv + eoff[rel];
        switch (rel) {
            case 0: R.x = tmpA;         R.ldx = 1024; break;
            case 1: R.x = tmpB;         R.ldx = 1536; break;
            case 2: R.x = tmpA + 512;   R.ldx = 1024; break;
            case 3: R.x = tmpB + 512;   R.ldx = 1536; break;
            default: R.x = tmpB + 1024; R.ldx = 1536; break;
        }
        return R;
    };
    auto round_to = [&](const float* s, float* d, size_t nelem) {
        size_t n4 = nelem / 4;
        tf32_round4<<<(unsigned)((n4 + 255) / 256), 256>>>(s, d, n4);
    };

    float* wA1 = wt + WA_off[0];
    float* wB1 = wt + WB_off[0];

    // Launch order: #4 is the big fused M=30000/N=1024/K=1024 gemm (profiled).
    do_wt(0, 0, wA1, 0);                              // 1
    do_wt(0, 2, wA1, 512);                            // 2
    round_to(feat0, f0t, (size_t)KN0 * KF);           // 3
    gemm(f0t, wA1, tmpA, KN0, 1024, KF);              // 4  <- profiled
    round_to(feat1, f1t, (size_t)KN1 * KF);           // 5
    do_wt(0, 1, wB1, 0);
    do_wt(0, 3, wB1, 512);
    do_wt(0, 4, wB1, 1024);
    gemm(f1t, wB1, tmpB, KN1, 1536, KF);
    for (int r = 0; r < 5; r++) build_csr(r);

    RelSrc dummy{};   // unused slots

    // ---------------- Layer 1: merged SpMM + fused epilogue -----------------
    spmm_multi<1, 2><<<(KN0 * 32 + 255) / 256, 256>>>(
        mkrel(0), mkrel(1), dummy, e00t, out, KN0, 0);
    spmm_multi<1, 3><<<(KN1 * 32 + 255) / 256, 256>>>(
        mkrel(2), mkrel(3), mkrel(4), e01t, out + (size_t)KN0 * LDO, KN1, 0);

    for (int l = 1; l < 3; l++) {
        do_wt(l, 0, wt + WA_off[l], 0);
        do_wt(l, 2, wt + WA_off[l], 512);
        do_wt(l, 1, wt + WB_off[l], 0);
        do_wt(l, 3, wt + WB_off[l], 512);
        do_wt(l, 4, wt + WB_off[l], 1024);
    }

    // ---------------- Layer 2 ----------------
    gemm(e00t, wt + WA_off[1], tmpA, KN0, 1024, KH);
    gemm(e01t, wt + WB_off[1], tmpB, KN1, 1536, KH);
    spmm_multi<2, 2><<<(KN0 * 32 + 255) / 256, 256>>>(
        mkrel(0), mkrel(1), dummy, e20t, nullptr, KN0, 0);
    spmm_multi<2, 3><<<(KN1 * 32 + 255) / 256, 256>>>(
        mkrel(2), mkrel(3), mkrel(4), e21t, nullptr, KN1, 0);

    // ---------------- Layer 3 (write-once into d_out cols 1024:1536) --------
    gemm(e20t, wt + WA_off[2], tmpA, KN0, 1024, KH);
    gemm(e21t, wt + WB_off[2], tmpB, KN1, 1536, KH);
    spmm_multi<0, 2><<<(KN0 * 32 + 255) / 256, 256>>>(
        mkrel(0), mkrel(1), dummy, out + 1024, nullptr, KN0, LDO);
    spmm_multi<0, 3><<<(KN1 * 32 + 255) / 256, 256>>>(
        mkrel(2), mkrel(3), mkrel(4), out + (size_t)KN0 * LDO + 1024, nullptr, KN1, LDO);
}